// round 8
// baseline (speedup 1.0000x reference)
#include <cuda_runtime.h>
#include <cuda_bf16.h>
#include <math.h>
#include <stdint.h>

// Problem constants
#define Bq 8
#define Sq 1024
#define Eq 512
#define Hq 8
#define Dq 64
#define BSq (Bq * Sq)
#define RS 48    // smem row stride bytes: 16 bf16 (32B) + 16B pad (conflict-free)
#define NST 4    // cp.async pipeline stages

// ---------------- global scratch (allocation-free) ----------------
__device__ __nv_bfloat16 g_inh[3 * BSq * Eq], g_inl[3 * BSq * Eq];   // q,k,v inputs (split)
__device__ __nv_bfloat16 g_wh[3 * Eq * Eq],  g_wl[3 * Eq * Eq];      // Wk,Wv,Wo (split)
__device__ __nv_bfloat16 g_qh[BSq * Eq], g_ql[BSq * Eq];             // q-proj planes
__device__ __nv_bfloat16 g_kh[BSq * Eq], g_kl[BSq * Eq];             // k-proj planes
__device__ __nv_bfloat16 g_vth[64 * Dq * Sq], g_vtl[64 * Dq * Sq];   // vT planes [bh][d][s]
__device__ __nv_bfloat16 g_ah[BSq * Eq], g_al[BSq * Eq];             // attn-out planes
__device__ __nv_bfloat16 g_ph[(size_t)64 * Sq * Sq], g_pl[(size_t)64 * Sq * Sq]; // P planes
__device__ float g_s[(size_t)64 * Sq * Sq];                          // raw scores fp32

// ---------------- PTX helpers ----------------
__device__ __forceinline__ uint32_t smem_u32(const void* p) {
    uint32_t a;
    asm("{ .reg .u64 t; cvta.to.shared.u64 t, %1; cvt.u32.u64 %0, t; }" : "=r"(a) : "l"(p));
    return a;
}
#define CPA16(sm, g) asm volatile("cp.async.ca.shared.global [%0], [%1], 16;" :: "r"(sm), "l"(g))
#define CPA_COMMIT() asm volatile("cp.async.commit_group;" ::: "memory")
#define CPA_WAIT(n)  asm volatile("cp.async.wait_group %0;" :: "n"(n) : "memory")

#define LDSM4(r, a) asm volatile( \
    "ldmatrix.sync.aligned.m8n8.x4.shared.b16 {%0,%1,%2,%3}, [%4];" \
    : "=r"((r)[0]), "=r"((r)[1]), "=r"((r)[2]), "=r"((r)[3]) : "r"(a))

#define MMA(d, a, b0, b1) asm volatile( \
    "mma.sync.aligned.m16n8k16.row.col.f32.bf16.bf16.f32 " \
    "{%0,%1,%2,%3}, {%4,%5,%6,%7}, {%8,%9}, {%0,%1,%2,%3};" \
    : "+f"((d)[0]), "+f"((d)[1]), "+f"((d)[2]), "+f"((d)[3]) \
    : "r"((a)[0]), "r"((a)[1]), "r"((a)[2]), "r"((a)[3]), "r"(b0), "r"(b1))

__device__ __forceinline__ void st_split2(__nv_bfloat16* h, __nv_bfloat16* l,
                                          size_t off, float x, float y) {
    __nv_bfloat162 h2 = __floats2bfloat162_rn(x, y);
    float2 f = __bfloat1622float2(h2);
    __nv_bfloat162 l2 = __floats2bfloat162_rn(x - f.x, y - f.y);
    *(__nv_bfloat162*)(h + off) = h2;
    *(__nv_bfloat162*)(l + off) = l2;
}

// ---------------- one-shot fp32 -> bf16 hi/lo split ----------------
__global__ void cvt_all(const float* __restrict__ q, const float* __restrict__ k,
                        const float* __restrict__ v, const float* __restrict__ Wk,
                        const float* __restrict__ Wv, const float* __restrict__ Wo) {
    const int NI = BSq * Eq / 4;
    const int NW = Eq * Eq / 4;
    const int total = 3 * NI + 3 * NW;
    for (int idx = blockIdx.x * blockDim.x + threadIdx.x; idx < total;
         idx += gridDim.x * blockDim.x) {
        const float* src; __nv_bfloat16 *h, *l; int off;
        if (idx < NI)                { src = q;  off = idx;               h = g_inh;               l = g_inl; }
        else if (idx < 2 * NI)       { src = k;  off = idx - NI;          h = g_inh + BSq * Eq;     l = g_inl + BSq * Eq; }
        else if (idx < 3 * NI)       { src = v;  off = idx - 2 * NI;      h = g_inh + 2 * BSq * Eq; l = g_inl + 2 * BSq * Eq; }
        else if (idx < 3 * NI + NW)  { src = Wk; off = idx - 3 * NI;      h = g_wh;                l = g_wl; }
        else if (idx < 3 * NI + 2 * NW) { src = Wv; off = idx - 3 * NI - NW; h = g_wh + Eq * Eq;   l = g_wl + Eq * Eq; }
        else                         { src = Wo; off = idx - 3 * NI - 2 * NW; h = g_wh + 2 * Eq * Eq; l = g_wl + 2 * Eq * Eq; }
        float4 x = ((const float4*)src)[off];
        __nv_bfloat162 h01 = __floats2bfloat162_rn(x.x, x.y);
        __nv_bfloat162 h23 = __floats2bfloat162_rn(x.z, x.w);
        float2 f01 = __bfloat1622float2(h01), f23 = __bfloat1622float2(h23);
        __nv_bfloat162 l01 = __floats2bfloat162_rn(x.x - f01.x, x.y - f01.y);
        __nv_bfloat162 l23 = __floats2bfloat162_rn(x.z - f23.x, x.w - f23.y);
        ((__nv_bfloat162*)h)[2 * off] = h01; ((__nv_bfloat162*)h)[2 * off + 1] = h23;
        ((__nv_bfloat162*)l)[2 * off] = l01; ((__nv_bfloat162*)l)[2 * off + 1] = l23;
    }
}

// ---------------- cp.async chunk staging (BK=16) ----------------
template<int BROWS>
__device__ __forceinline__ void issue_chunk(uint32_t sbuf,
    const __nv_bfloat16* __restrict__ Ah, const __nv_bfloat16* __restrict__ Al, int lda,
    const __nv_bfloat16* __restrict__ Bh, const __nv_bfloat16* __restrict__ Bl, int ldb,
    int c, int tid) {
    const int PA = 128 * RS, PB = BROWS * RS;
    {   // A: 128 rows x 2 units; one unit per thread
        const int row = tid >> 1, u = tid & 1;
        const uint32_t so = sbuf + row * RS + u * 16;
        const size_t go = (size_t)row * lda + c * 16 + u * 8;
        CPA16(so, Ah + go);
        CPA16(so + PA, Al + go);
    }
    if (BROWS == 128) {
        const int row = tid >> 1, u = tid & 1;
        const uint32_t so = sbuf + 2 * PA + row * RS + u * 16;
        const size_t go = (size_t)row * ldb + c * 16 + u * 8;
        CPA16(so, Bh + go);
        CPA16(so + PB, Bl + go);
    } else if (tid < BROWS * 2) {
        const int row = tid >> 1, u = tid & 1;
        const uint32_t so = sbuf + 2 * PA + row * RS + u * 16;
        const size_t go = (size_t)row * ldb + c * 16 + u * 8;
        CPA16(so, Bh + go);
        CPA16(so + PB, Bl + go);
    }
    CPA_COMMIT();
}

// Core: acc += A[128,K] . B[BROWS,K]^T, 2-term bf16 split (hh + lh + hl).
// 4-stage cp.async ring, one __syncthreads per 16-K chunk.
template<int BROWS, int NT>
__device__ __forceinline__ void mma_core(uint32_t smb,
    const __nv_bfloat16* Ah, const __nv_bfloat16* Al, int lda,
    const __nv_bfloat16* Bh, const __nv_bfloat16* Bl, int ldb,
    int n, int tid, float acc[4][NT][4]) {
    const int PA = 128 * RS, PB = BROWS * RS, STG = 2 * PA + 2 * PB;
    const int wid = tid >> 5, lane = tid & 31;
    const int wm = wid & 1, wn = wid >> 1;
    const uint32_t aoff = (uint32_t)((wm * 64 + (lane & 15)) * RS + ((lane >> 4) << 4));
    const uint32_t bi = lane >> 3;
    const uint32_t boff = (uint32_t)((wn * (NT * 8) + ((bi >> 1) << 3) + (lane & 7)) * RS +
                                     ((bi & 1) << 4));

#pragma unroll
    for (int s = 0; s < NST - 1; ++s)
        if (s < n) issue_chunk<BROWS>(smb + s * STG, Ah, Al, lda, Bh, Bl, ldb, s, tid);

    for (int c = 0; c < n; ++c) {
        const int rem = n - 1 - c;
        if (rem >= 2)      { CPA_WAIT(2); }
        else if (rem == 1) { CPA_WAIT(1); }
        else               { CPA_WAIT(0); }
        __syncthreads();
        if (c + NST - 1 < n)
            issue_chunk<BROWS>(smb + ((c + NST - 1) % NST) * STG, Ah, Al, lda, Bh, Bl, ldb,
                               c + NST - 1, tid);
        const uint32_t AHb = smb + (c % NST) * STG, ALb = AHb + PA;
        const uint32_t BHb = AHb + 2 * PA, BLb = BHb + PB;

        uint32_t ah[4][4], al[4][4];
        uint32_t bh[(NT + 1) / 2][4], bl[(NT + 1) / 2][4];
#pragma unroll
        for (int mt = 0; mt < 4; ++mt) {
            LDSM4(ah[mt], AHb + aoff + mt * 16 * RS);
            LDSM4(al[mt], ALb + aoff + mt * 16 * RS);
        }
#pragma unroll
        for (int p = 0; p < (NT + 1) / 2; ++p) {
            LDSM4(bh[p], BHb + boff + p * 16 * RS);
            LDSM4(bl[p], BLb + boff + p * 16 * RS);
        }
#pragma unroll
        for (int mt = 0; mt < 4; ++mt)
#pragma unroll
            for (int nt = 0; nt < NT; ++nt) {
                const uint32_t b0h = bh[nt >> 1][(nt & 1) * 2];
                const uint32_t b1h = bh[nt >> 1][(nt & 1) * 2 + 1];
                const uint32_t b0l = bl[nt >> 1][(nt & 1) * 2];
                const uint32_t b1l = bl[nt >> 1][(nt & 1) * 2 + 1];
                MMA(acc[mt][nt], ah[mt], b0h, b1h);   // hi*hi
                MMA(acc[mt][nt], al[mt], b0h, b1h);   // lo*hi
                MMA(acc[mt][nt], ah[mt], b0l, b1l);   // hi*lo
            }
    }
}

// ---------------------------------------------------------------------------
// Input projections, merged: blockIdx.z = 0 (q->Wk->g_q), 1 (k->Wk->g_k),
// 2 (v->Wv->g_vT transposed).
// ---------------------------------------------------------------------------
__global__ __launch_bounds__(256, 2) void proj_in(const float* __restrict__ bk,
                                                  const float* __restrict__ bv) {
    extern __shared__ __align__(16) char sm[];
    const uint32_t smb = smem_u32(sm);
    const int tid = threadIdx.x, wid = tid >> 5, lane = tid & 31;
    const int wm = wid & 1, wn = wid >> 1;
    const int bm = blockIdx.y * 128, bn = blockIdx.x * 128;
    const int z = blockIdx.z;

    const float* bias = (z == 2) ? bv : bk;
    const int bsel = (z == 2) ? 1 : 0;
    const __nv_bfloat16* Ah = g_inh + (size_t)z * BSq * Eq + (size_t)bm * Eq;
    const __nv_bfloat16* Al = g_inl + (size_t)z * BSq * Eq + (size_t)bm * Eq;
    const __nv_bfloat16* Bh = g_wh + (size_t)bsel * Eq * Eq + (size_t)bn * Eq;
    const __nv_bfloat16* Bl = g_wl + (size_t)bsel * Eq * Eq + (size_t)bn * Eq;

    float acc[4][4][4];
#pragma unroll
    for (int a = 0; a < 4; ++a)
#pragma unroll
        for (int b = 0; b < 4; ++b)
#pragma unroll
            for (int c = 0; c < 4; ++c) acc[a][b][c] = 0.f;

    mma_core<128, 4>(smb, Ah, Al, Eq, Bh, Bl, Eq, Eq / 16, tid, acc);
    __syncthreads();

    if (z != 2) {
        __nv_bfloat16* Ch = (z == 0) ? g_qh : g_kh;
        __nv_bfloat16* Cl = (z == 0) ? g_ql : g_kl;
#pragma unroll
        for (int mt = 0; mt < 4; ++mt)
#pragma unroll
            for (int nt = 0; nt < 4; ++nt) {
                const int row = bm + wm * 64 + mt * 16 + (lane >> 2);
                const int col = bn + wn * 32 + nt * 8 + ((lane & 3) << 1);
                const float2 bb = *(const float2*)(bias + col);
                st_split2(Ch, Cl, (size_t)row * Eq + col,
                          acc[mt][nt][0] + bb.x, acc[mt][nt][1] + bb.y);
                st_split2(Ch, Cl, (size_t)(row + 8) * Eq + col,
                          acc[mt][nt][2] + bb.x, acc[mt][nt][3] + bb.y);
            }
    } else {
        // transpose through smem into g_vT planes [bh][d][s]
        float (*smt)[65] = (float(*)[65])sm;
#pragma unroll
        for (int hf = 0; hf < 2; ++hf) {
            if ((wn >> 1) == hf) {
#pragma unroll
                for (int mt = 0; mt < 4; ++mt)
#pragma unroll
                    for (int nt = 0; nt < 4; ++nt) {
                        const int row = wm * 64 + mt * 16 + (lane >> 2);
                        const int colL = (wn & 1) * 32 + nt * 8 + ((lane & 3) << 1);
                        const int colG = bn + hf * 64 + colL;
                        const float2 bb = *(const float2*)(bias + colG);
                        smt[row][colL] = acc[mt][nt][0] + bb.x;
                        smt[row][colL + 1] = acc[mt][nt][1] + bb.y;
                        smt[row + 8][colL] = acc[mt][nt][2] + bb.x;
                        smt[row + 8][colL + 1] = acc[mt][nt][3] + bb.y;
                    }
            }
            __syncthreads();
            {
                const int colL = tid & 63, seg = (tid >> 6) << 5;
                const int n2 = bn + hf * 64 + colL;
                const size_t dbase = ((size_t)((bm >> 10) * 8 + (n2 >> 6)) << 16) +
                                     ((size_t)(n2 & 63) << 10) + (bm & 1023) + seg;
#pragma unroll
                for (int i = 0; i < 8; ++i) {
                    const float a0 = smt[seg + 4 * i][colL], a1 = smt[seg + 4 * i + 1][colL];
                    const float a2 = smt[seg + 4 * i + 2][colL], a3 = smt[seg + 4 * i + 3][colL];
                    st_split2(g_vth, g_vtl, dbase + 4 * i, a0, a1);
                    st_split2(g_vth, g_vtl, dbase + 4 * i + 2, a2, a3);
                }
            }
            __syncthreads();
        }
    }
}

// ---------------------------------------------------------------------------
// Output projection: d_out = attn_out @ Wo^T + bo  (fp32 result)
// ---------------------------------------------------------------------------
__global__ __launch_bounds__(256, 2) void proj_out(const float* __restrict__ bias,
                                                   float* __restrict__ Cp) {
    extern __shared__ __align__(16) char sm[];
    const uint32_t smb = smem_u32(sm);
    const int tid = threadIdx.x, wid = tid >> 5, lane = tid & 31;
    const int wm = wid & 1, wn = wid >> 1;
    const int bm = blockIdx.y * 128, bn = blockIdx.x * 128;

    const __nv_bfloat16* Ah = g_ah + (size_t)bm * Eq;
    const __nv_bfloat16* Al = g_al + (size_t)bm * Eq;
    const __nv_bfloat16* Bh = g_wh + (size_t)2 * Eq * Eq + (size_t)bn * Eq;
    const __nv_bfloat16* Bl = g_wl + (size_t)2 * Eq * Eq + (size_t)bn * Eq;

    float acc[4][4][4];
#pragma unroll
    for (int a = 0; a < 4; ++a)
#pragma unroll
        for (int b = 0; b < 4; ++b)
#pragma unroll
            for (int c = 0; c < 4; ++c) acc[a][b][c] = 0.f;

    mma_core<128, 4>(smb, Ah, Al, Eq, Bh, Bl, Eq, Eq / 16, tid, acc);

#pragma unroll
    for (int mt = 0; mt < 4; ++mt)
#pragma unroll
        for (int nt = 0; nt < 4; ++nt) {
            const int row = bm + wm * 64 + mt * 16 + (lane >> 2);
            const int col = bn + wn * 32 + nt * 8 + ((lane & 3) << 1);
            const float2 bb = *(const float2*)(bias + col);
            float2 o0, o1;
            o0.x = acc[mt][nt][0] + bb.x; o0.y = acc[mt][nt][1] + bb.y;
            o1.x = acc[mt][nt][2] + bb.x; o1.y = acc[mt][nt][3] + bb.y;
            *(float2*)(Cp + (size_t)row * Eq + col) = o0;
            *(float2*)(Cp + (size_t)(row + 8) * Eq + col) = o1;
        }
}

// ---------------------------------------------------------------------------
// QK^T: S = (1/8) q . k^T per (b,h); causal tile skip. K=64 (4 chunks).
// ---------------------------------------------------------------------------
__global__ __launch_bounds__(256, 2) void qk_mma() {
    const int bx = blockIdx.x, by = blockIdx.y;
    if (by < bx) return;
    extern __shared__ __align__(16) char sm[];
    const uint32_t smb = smem_u32(sm);
    const int tid = threadIdx.x, wid = tid >> 5, lane = tid & 31;
    const int wm = wid & 1, wn = wid >> 1;
    const int bh = blockIdx.z, b = bh >> 3, h = bh & 7;
    const int bm = by * 128, bn = bx * 128;

    const size_t abase = (size_t)(b * Sq + bm) * Eq + h * Dq;
    const size_t bbase = (size_t)(b * Sq + bn) * Eq + h * Dq;

    float acc[4][4][4];
#pragma unroll
    for (int a = 0; a < 4; ++a)
#pragma unroll
        for (int c = 0; c < 4; ++c)
#pragma unroll
            for (int d = 0; d < 4; ++d) acc[a][c][d] = 0.f;

    mma_core<128, 4>(smb, g_qh + abase, g_ql + abase, Eq,
                     g_kh + bbase, g_kl + bbase, Eq, Dq / 16, tid, acc);

    float* S = g_s + ((size_t)bh << 20);
#pragma unroll
    for (int mt = 0; mt < 4; ++mt)
#pragma unroll
        for (int nt = 0; nt < 4; ++nt) {
            const int row = bm + wm * 64 + mt * 16 + (lane >> 2);
            const int col = bn + wn * 32 + nt * 8 + ((lane & 3) << 1);
            float2 o0, o1;
            o0.x = acc[mt][nt][0] * 0.125f; o0.y = acc[mt][nt][1] * 0.125f;
            o1.x = acc[mt][nt][2] * 0.125f; o1.y = acc[mt][nt][3] * 0.125f;
            *(float2*)(S + (size_t)row * Sq + col) = o0;
            *(float2*)(S + (size_t)(row + 8) * Sq + col) = o1;
        }
}

// ---------------------------------------------------------------------------
// PV: out[i,d] = sum_j P[i,j] * VT[d,j].  BN=64, K extent = bm+128 (causal).
// ---------------------------------------------------------------------------
__global__ __launch_bounds__(256, 2) void pv_mma() {
    extern __shared__ __align__(16) char sm[];
    const uint32_t smb = smem_u32(sm);
    const int tid = threadIdx.x, wid = tid >> 5, lane = tid & 31;
    const int wm = wid & 1, wn = wid >> 1;
    const int bh = blockIdx.y, b = bh >> 3, h = bh & 7;
    const int bm = (7 - (int)blockIdx.x) * 128;   // heavy tiles first

    const size_t pbase = ((size_t)bh << 20) + (size_t)bm * Sq;
    const size_t vbase = (size_t)bh * (Dq * Sq);

    float acc[4][2][4];
#pragma unroll
    for (int a = 0; a < 4; ++a)
#pragma unroll
        for (int c = 0; c < 2; ++c)
#pragma unroll
            for (int d = 0; d < 4; ++d) acc[a][c][d] = 0.f;

    mma_core<64, 2>(smb, g_ph + pbase, g_pl + pbase, Sq,
                    g_vth + vbase, g_vtl + vbase, Sq, bm / 16 + 8, tid, acc);

#pragma unroll
    for (int mt = 0; mt < 4; ++mt)
#pragma unroll
        for (int nt = 0; nt < 2; ++nt) {
            const int row = b * Sq + bm + wm * 64 + mt * 16 + (lane >> 2);
            const int col = h * Dq + wn * 16 + nt * 8 + ((lane & 3) << 1);
            st_split2(g_ah, g_al, (size_t)row * Eq + col, acc[mt][nt][0], acc[mt][nt][1]);
            st_split2(g_ah, g_al, (size_t)(row + 8) * Eq + col, acc[mt][nt][2], acc[mt][nt][3]);
        }
}

// ---------------------------------------------------------------------------
// Softmax + distance-decay + second softmax; causal-aware; writes P planes.
// ---------------------------------------------------------------------------
__device__ __forceinline__ float wmax(float v) {
#pragma unroll
    for (int o = 16; o > 0; o >>= 1) v = fmaxf(v, __shfl_xor_sync(0xffffffffu, v, o));
    return v;
}
__device__ __forceinline__ float wsum(float v) {
#pragma unroll
    for (int o = 16; o > 0; o >>= 1) v += __shfl_xor_sync(0xffffffffu, v, o);
    return v;
}

__global__ __launch_bounds__(256) void softmax_decay(const float* __restrict__ gammas) {
    const int warp = threadIdx.x >> 5;
    const int lane = threadIdx.x & 31;
    const int r = blockIdx.x * 8 + warp;
    const int i = r & (Sq - 1);
    const int h = (r >> 10) & (Hq - 1);
    const float* Srow = g_s + (size_t)r * Sq;

    const float gv = gammas[h];
    const float gamma = -(fmaxf(gv, 0.f) + log1pf(__expf(-fabsf(gv))));
    const float NEGINF = -INFINITY;

    const int j0 = lane * 32;
    float s[32];
    if (j0 <= i) {
#pragma unroll
        for (int t = 0; t < 8; t++) ((float4*)s)[t] = ((const float4*)(Srow + j0))[t];
#pragma unroll
        for (int t = 0; t < 32; t++) if (j0 + t > i) s[t] = NEGINF;
    } else {
#pragma unroll
        for (int t = 0; t < 32; t++) s[t] = NEGINF;
    }

    float m1 = NEGINF;
#pragma unroll
    for (int t = 0; t < 32; t++) m1 = fmaxf(m1, s[t]);
    m1 = wmax(m1);

    float p[32];
    float ls = 0.f;
#pragma unroll
    for (int t = 0; t < 32; t++) { p[t] = __expf(s[t] - m1); ls += p[t]; }
    const float inv1 = 1.f / wsum(ls);

#pragma unroll
    for (int t = 1; t < 32; t++) p[t] += p[t - 1];
    float tot = p[31];
    float x = tot;
#pragma unroll
    for (int off = 1; off < 32; off <<= 1) {
        const float tv = __shfl_up_sync(0xffffffffu, x, off);
        if (lane >= off) x += tv;
    }
    const float excl = x - tot;

    float m2 = NEGINF;
#pragma unroll
    for (int t = 0; t < 32; t++) {
        const int j = j0 + t;
        const float Cj = (excl + p[t]) * inv1;
        const float pd = fmaxf((1.f - Cj) * (float)(i - j), 0.f);
        float eff = __expf(gamma * sqrtf(pd));
        eff = fminf(fmaxf(eff, 1e-5f), 1e5f);
        s[t] *= eff;
        m2 = fmaxf(m2, s[t]);
    }
    m2 = wmax(m2);

    float l2 = 0.f;
#pragma unroll
    for (int t = 0; t < 32; t++) { p[t] = __expf(s[t] - m2); l2 += p[t]; }
    const float scale = ((i == 0) ? 0.f : 1.f) / wsum(l2);
#pragma unroll
    for (int t = 0; t < 32; t++) p[t] *= scale;

    if (j0 < (((i >> 7) + 1) << 7)) {   // pv reads only up to the row's diagonal tile
        uint32_t hw[16], lw[16];
#pragma unroll
        for (int t = 0; t < 32; t += 2) {
            __nv_bfloat162 h2 = __floats2bfloat162_rn(p[t], p[t + 1]);
            float2 f = __bfloat1622float2(h2);
            __nv_bfloat162 l2v = __floats2bfloat162_rn(p[t] - f.x, p[t + 1] - f.y);
            hw[t >> 1] = *(uint32_t*)&h2;
            lw[t >> 1] = *(uint32_t*)&l2v;
        }
        uint4* dh = (uint4*)(g_ph + (size_t)r * Sq + j0);
        uint4* dl = (uint4*)(g_pl + (size_t)r * Sq + j0);
#pragma unroll
        for (int w = 0; w < 4; ++w) { dh[w] = ((uint4*)hw)[w]; dl[w] = ((uint4*)lw)[w]; }
    }
}

// ---------------------------------------------------------------------------
extern "C" void kernel_launch(void* const* d_in, const int* in_sizes, int n_in,
                              void* d_out, int out_size) {
    const float* q      = (const float*)d_in[0];
    const float* k      = (const float*)d_in[1];
    const float* v      = (const float*)d_in[2];
    const float* Wk     = (const float*)d_in[3];
    const float* bk     = (const float*)d_in[4];
    const float* Wv     = (const float*)d_in[5];
    const float* bv     = (const float*)d_in[6];
    const float* Wo     = (const float*)d_in[7];
    const float* bo     = (const float*)d_in[8];
    const float* gammas = (const float*)d_in[9];

    const int STG_128 = 2 * 128 * RS + 2 * 128 * RS;   // 24576
    const int STG_64  = 2 * 128 * RS + 2 * 64 * RS;    // 18432
    const int SM_128 = NST * STG_128;                  // 98304
    const int SM_64  = NST * STG_64;                   // 73728
    cudaFuncSetAttribute(proj_in,  cudaFuncAttributeMaxDynamicSharedMemorySize, SM_128);
    cudaFuncSetAttribute(proj_out, cudaFuncAttributeMaxDynamicSharedMemorySize, SM_128);
    cudaFuncSetAttribute(qk_mma,   cudaFuncAttributeMaxDynamicSharedMemorySize, SM_128);
    cudaFuncSetAttribute(pv_mma,   cudaFuncAttributeMaxDynamicSharedMemorySize, SM_64);

    cvt_all<<<1024, 256>>>(q, k, v, Wk, Wv, Wo);
    proj_in<<<dim3(4, 64, 3), 256, SM_128>>>(bk, bv);                // g_q, g_k, g_vT planes
    qk_mma<<<dim3(8, 8, 64), 256, SM_128>>>();                       // g_s = scores
    softmax_decay<<<(64 * Sq) / 8, 256>>>(gammas);                   // P planes
    pv_mma<<<dim3(8, 64), 256, SM_64>>>();                           // g_a planes
    proj_out<<<dim3(4, 64), 256, SM_128>>>(bo, (float*)d_out);       // final fp32
}

// round 9
// speedup vs baseline: 1.2248x; 1.2248x over previous
#include <cuda_runtime.h>
#include <cuda_bf16.h>
#include <math.h>
#include <stdint.h>

// Problem constants
#define Bq 8
#define Sq 1024
#define Eq 512
#define Hq 8
#define Dq 64
#define BSq (Bq * Sq)
#define RS 80   // smem row stride bytes: 32 bf16 (64B) + 16B pad

// ---------------- global scratch (allocation-free) ----------------
__device__ __nv_bfloat16 g_inh[3 * BSq * Eq], g_inl[3 * BSq * Eq];   // q,k,v inputs (split)
__device__ __nv_bfloat16 g_wh[3 * Eq * Eq],  g_wl[3 * Eq * Eq];      // Wk,Wv,Wo (split)
__device__ __nv_bfloat16 g_qh[BSq * Eq], g_ql[BSq * Eq];             // q-proj planes
__device__ __nv_bfloat16 g_kh[BSq * Eq], g_kl[BSq * Eq];             // k-proj planes
__device__ __nv_bfloat16 g_vth[64 * Dq * Sq], g_vtl[64 * Dq * Sq];   // vT planes [bh][d][s]
__device__ __nv_bfloat16 g_ah[BSq * Eq], g_al[BSq * Eq];             // attn-out planes
__device__ __nv_bfloat16 g_ph[(size_t)64 * Sq * Sq], g_pl[(size_t)64 * Sq * Sq]; // P planes
__device__ float g_s[(size_t)64 * Sq * Sq];                          // raw scores fp32

// ---------------- PTX helpers ----------------
__device__ __forceinline__ uint32_t smem_u32(const void* p) {
    uint32_t a;
    asm("{ .reg .u64 t; cvta.to.shared.u64 t, %1; cvt.u32.u64 %0, t; }" : "=r"(a) : "l"(p));
    return a;
}
#define CPA16(sm, g) asm volatile("cp.async.ca.shared.global [%0], [%1], 16;" :: "r"(sm), "l"(g))
#define CPA_COMMIT() asm volatile("cp.async.commit_group;" ::: "memory")
#define CPA_WAIT(n)  asm volatile("cp.async.wait_group %0;" :: "n"(n) : "memory")

#define LDSM4(r, a) asm volatile( \
    "ldmatrix.sync.aligned.m8n8.x4.shared.b16 {%0,%1,%2,%3}, [%4];" \
    : "=r"((r)[0]), "=r"((r)[1]), "=r"((r)[2]), "=r"((r)[3]) : "r"(a))

#define MMA(d, a, b0, b1) asm volatile( \
    "mma.sync.aligned.m16n8k16.row.col.f32.bf16.bf16.f32 " \
    "{%0,%1,%2,%3}, {%4,%5,%6,%7}, {%8,%9}, {%0,%1,%2,%3};" \
    : "+f"((d)[0]), "+f"((d)[1]), "+f"((d)[2]), "+f"((d)[3]) \
    : "r"((a)[0]), "r"((a)[1]), "r"((a)[2]), "r"((a)[3]), "r"(b0), "r"(b1))

__device__ __forceinline__ void st_split2(__nv_bfloat16* h, __nv_bfloat16* l,
                                          size_t off, float x, float y) {
    __nv_bfloat162 h2 = __floats2bfloat162_rn(x, y);
    float2 f = __bfloat1622float2(h2);
    __nv_bfloat162 l2 = __floats2bfloat162_rn(x - f.x, y - f.y);
    *(__nv_bfloat162*)(h + off) = h2;
    *(__nv_bfloat162*)(l + off) = l2;
}

// ---------------- one-shot fp32 -> bf16 hi/lo split ----------------
__global__ void cvt_all(const float* __restrict__ q, const float* __restrict__ k,
                        const float* __restrict__ v, const float* __restrict__ Wk,
                        const float* __restrict__ Wv, const float* __restrict__ Wo) {
    const int NI = BSq * Eq / 4;
    const int NW = Eq * Eq / 4;
    const int total = 3 * NI + 3 * NW;
    for (int idx = blockIdx.x * blockDim.x + threadIdx.x; idx < total;
         idx += gridDim.x * blockDim.x) {
        const float* src; __nv_bfloat16 *h, *l; int off;
        if (idx < NI)                { src = q;  off = idx;               h = g_inh;               l = g_inl; }
        else if (idx < 2 * NI)       { src = k;  off = idx - NI;          h = g_inh + BSq * Eq;     l = g_inl + BSq * Eq; }
        else if (idx < 3 * NI)       { src = v;  off = idx - 2 * NI;      h = g_inh + 2 * BSq * Eq; l = g_inl + 2 * BSq * Eq; }
        else if (idx < 3 * NI + NW)  { src = Wk; off = idx - 3 * NI;      h = g_wh;                l = g_wl; }
        else if (idx < 3 * NI + 2 * NW) { src = Wv; off = idx - 3 * NI - NW; h = g_wh + Eq * Eq;   l = g_wl + Eq * Eq; }
        else                         { src = Wo; off = idx - 3 * NI - 2 * NW; h = g_wh + 2 * Eq * Eq; l = g_wl + 2 * Eq * Eq; }
        float4 x = ((const float4*)src)[off];
        __nv_bfloat162 h01 = __floats2bfloat162_rn(x.x, x.y);
        __nv_bfloat162 h23 = __floats2bfloat162_rn(x.z, x.w);
        float2 f01 = __bfloat1622float2(h01), f23 = __bfloat1622float2(h23);
        __nv_bfloat162 l01 = __floats2bfloat162_rn(x.x - f01.x, x.y - f01.y);
        __nv_bfloat162 l23 = __floats2bfloat162_rn(x.z - f23.x, x.w - f23.y);
        ((__nv_bfloat162*)h)[2 * off] = h01; ((__nv_bfloat162*)h)[2 * off + 1] = h23;
        ((__nv_bfloat162*)l)[2 * off] = l01; ((__nv_bfloat162*)l)[2 * off + 1] = l23;
    }
}

// ---------------- cp.async chunk staging (BK=32, R7 config) ----------------
template<int BROWS>
__device__ __forceinline__ void issue_chunk(uint32_t sbuf, int PA, int PB,
    const __nv_bfloat16* __restrict__ Ah, const __nv_bfloat16* __restrict__ Al, int lda,
    const __nv_bfloat16* __restrict__ Bh, const __nv_bfloat16* __restrict__ Bl, int ldb,
    int c, int tid) {
#pragma unroll
    for (int it = 0; it < 2; ++it) {                 // A: 128 rows x 4 16B-units
        const int u = tid + it * 256;
        const int row = u >> 2, q16 = u & 3;
        const uint32_t so = sbuf + row * RS + q16 * 16;
        const size_t go = (size_t)row * lda + c * 32 + q16 * 8;
        CPA16(so, Ah + go);
        CPA16(so + PA, Al + go);
    }
#pragma unroll
    for (int it = 0; it < (BROWS * 4) / 256; ++it) { // B: BROWS rows x 4 units
        const int u = tid + it * 256;
        const int row = u >> 2, q16 = u & 3;
        const uint32_t so = sbuf + 2 * PA + row * RS + q16 * 16;
        const size_t go = (size_t)row * ldb + c * 32 + q16 * 8;
        CPA16(so, Bh + go);
        CPA16(so + PB, Bl + go);
    }
    CPA_COMMIT();
}

// Core: acc += A[128,K] . B[BROWS,K]^T, 2-term bf16 split (hh + lh + hl).
// cp.async double-buffered (R7 config, BK=32).
template<int BROWS, int NT>
__device__ __forceinline__ void mma_core(uint32_t smb,
    const __nv_bfloat16* Ah, const __nv_bfloat16* Al, int lda,
    const __nv_bfloat16* Bh, const __nv_bfloat16* Bl, int ldb,
    int nchunks, int tid, float acc[4][NT][4]) {
    const int PA = 128 * RS, PB = BROWS * RS, BUF = 2 * PA + 2 * PB;
    const int wid = tid >> 5, lane = tid & 31;
    const int wm = wid & 1, wn = wid >> 1;
    const uint32_t aoff = (uint32_t)((wm * 64 + (lane & 15)) * RS + ((lane >> 4) << 4));
    const uint32_t bi = lane >> 3;
    const uint32_t boff = (uint32_t)((wn * (NT * 8) + ((bi >> 1) << 3) + (lane & 7)) * RS +
                                     ((bi & 1) << 4));

    issue_chunk<BROWS>(smb, PA, PB, Ah, Al, lda, Bh, Bl, ldb, 0, tid);
    for (int c = 0; c < nchunks; ++c) {
        if (c + 1 < nchunks) {
            issue_chunk<BROWS>(smb + ((c + 1) & 1) * BUF, PA, PB, Ah, Al, lda, Bh, Bl, ldb,
                               c + 1, tid);
            CPA_WAIT(1);
        } else {
            CPA_WAIT(0);
        }
        __syncthreads();
        const uint32_t AHb = smb + (c & 1) * BUF, ALb = AHb + PA;
        const uint32_t BHb = AHb + 2 * PA, BLb = BHb + PB;
#pragma unroll
        for (int s = 0; s < 2; ++s) {
            uint32_t ah[4][4], al[4][4];
            uint32_t bh[(NT + 1) / 2][4], bl[(NT + 1) / 2][4];
            const uint32_t so = s * 32;
#pragma unroll
            for (int mt = 0; mt < 4; ++mt) {
                LDSM4(ah[mt], AHb + aoff + mt * 16 * RS + so);
                LDSM4(al[mt], ALb + aoff + mt * 16 * RS + so);
            }
#pragma unroll
            for (int p = 0; p < (NT + 1) / 2; ++p) {
                LDSM4(bh[p], BHb + boff + p * 16 * RS + so);
                LDSM4(bl[p], BLb + boff + p * 16 * RS + so);
            }
#pragma unroll
            for (int mt = 0; mt < 4; ++mt)
#pragma unroll
                for (int nt = 0; nt < NT; ++nt) {
                    const uint32_t b0h = bh[nt >> 1][(nt & 1) * 2];
                    const uint32_t b1h = bh[nt >> 1][(nt & 1) * 2 + 1];
                    const uint32_t b0l = bl[nt >> 1][(nt & 1) * 2];
                    const uint32_t b1l = bl[nt >> 1][(nt & 1) * 2 + 1];
                    MMA(acc[mt][nt], ah[mt], b0h, b1h);   // hi*hi
                    MMA(acc[mt][nt], al[mt], b0h, b1h);   // lo*hi
                    MMA(acc[mt][nt], ah[mt], b0l, b1l);   // hi*lo
                }
        }
        __syncthreads();
    }
}

// ---------------------------------------------------------------------------
// Input projections, merged: blockIdx.z = 0 (q->Wk->g_q), 1 (k->Wk->g_k),
// 2 (v->Wv->g_vT transposed).
// ---------------------------------------------------------------------------
__global__ __launch_bounds__(256, 2) void proj_in(const float* __restrict__ bk,
                                                  const float* __restrict__ bv) {
    extern __shared__ __align__(16) char sm[];
    const uint32_t smb = smem_u32(sm);
    const int tid = threadIdx.x, wid = tid >> 5, lane = tid & 31;
    const int wm = wid & 1, wn = wid >> 1;
    const int bm = blockIdx.y * 128, bn = blockIdx.x * 128;
    const int z = blockIdx.z;

    const float* bias = (z == 2) ? bv : bk;
    const int bsel = (z == 2) ? 1 : 0;
    const __nv_bfloat16* Ah = g_inh + (size_t)z * BSq * Eq + (size_t)bm * Eq;
    const __nv_bfloat16* Al = g_inl + (size_t)z * BSq * Eq + (size_t)bm * Eq;
    const __nv_bfloat16* Bh = g_wh + (size_t)bsel * Eq * Eq + (size_t)bn * Eq;
    const __nv_bfloat16* Bl = g_wl + (size_t)bsel * Eq * Eq + (size_t)bn * Eq;

    float acc[4][4][4];
#pragma unroll
    for (int a = 0; a < 4; ++a)
#pragma unroll
        for (int b = 0; b < 4; ++b)
#pragma unroll
            for (int c = 0; c < 4; ++c) acc[a][b][c] = 0.f;

    mma_core<128, 4>(smb, Ah, Al, Eq, Bh, Bl, Eq, Eq / 32, tid, acc);

    if (z != 2) {
        __nv_bfloat16* Ch = (z == 0) ? g_qh : g_kh;
        __nv_bfloat16* Cl = (z == 0) ? g_ql : g_kl;
#pragma unroll
        for (int mt = 0; mt < 4; ++mt)
#pragma unroll
            for (int nt = 0; nt < 4; ++nt) {
                const int row = bm + wm * 64 + mt * 16 + (lane >> 2);
                const int col = bn + wn * 32 + nt * 8 + ((lane & 3) << 1);
                const float2 bb = *(const float2*)(bias + col);
                st_split2(Ch, Cl, (size_t)row * Eq + col,
                          acc[mt][nt][0] + bb.x, acc[mt][nt][1] + bb.y);
                st_split2(Ch, Cl, (size_t)(row + 8) * Eq + col,
                          acc[mt][nt][2] + bb.x, acc[mt][nt][3] + bb.y);
            }
    } else {
        // transpose through smem into g_vT planes [bh][d][s]
        float (*smt)[65] = (float(*)[65])sm;
#pragma unroll
        for (int hf = 0; hf < 2; ++hf) {
            if ((wn >> 1) == hf) {
#pragma unroll
                for (int mt = 0; mt < 4; ++mt)
#pragma unroll
                    for (int nt = 0; nt < 4; ++nt) {
                        const int row = wm * 64 + mt * 16 + (lane >> 2);
                        const int colL = (wn & 1) * 32 + nt * 8 + ((lane & 3) << 1);
                        const int colG = bn + hf * 64 + colL;
                        const float2 bb = *(const float2*)(bias + colG);
                        smt[row][colL] = acc[mt][nt][0] + bb.x;
                        smt[row][colL + 1] = acc[mt][nt][1] + bb.y;
                        smt[row + 8][colL] = acc[mt][nt][2] + bb.x;
                        smt[row + 8][colL + 1] = acc[mt][nt][3] + bb.y;
                    }
            }
            __syncthreads();
            {
                const int colL = tid & 63, seg = (tid >> 6) << 5;
                const int n2 = bn + hf * 64 + colL;
                const size_t dbase = ((size_t)((bm >> 10) * 8 + (n2 >> 6)) << 16) +
                                     ((size_t)(n2 & 63) << 10) + (bm & 1023) + seg;
#pragma unroll
                for (int i = 0; i < 8; ++i) {
                    const float a0 = smt[seg + 4 * i][colL], a1 = smt[seg + 4 * i + 1][colL];
                    const float a2 = smt[seg + 4 * i + 2][colL], a3 = smt[seg + 4 * i + 3][colL];
                    st_split2(g_vth, g_vtl, dbase + 4 * i, a0, a1);
                    st_split2(g_vth, g_vtl, dbase + 4 * i + 2, a2, a3);
                }
            }
            __syncthreads();
        }
    }
}

// ---------------------------------------------------------------------------
// Output projection: d_out = attn_out @ Wo^T + bo  (fp32 result)
// ---------------------------------------------------------------------------
__global__ __launch_bounds__(256, 2) void proj_out(const float* __restrict__ bias,
                                                   float* __restrict__ Cp) {
    extern __shared__ __align__(16) char sm[];
    const uint32_t smb = smem_u32(sm);
    const int tid = threadIdx.x, wid = tid >> 5, lane = tid & 31;
    const int wm = wid & 1, wn = wid >> 1;
    const int bm = blockIdx.y * 128, bn = blockIdx.x * 128;

    const __nv_bfloat16* Ah = g_ah + (size_t)bm * Eq;
    const __nv_bfloat16* Al = g_al + (size_t)bm * Eq;
    const __nv_bfloat16* Bh = g_wh + (size_t)2 * Eq * Eq + (size_t)bn * Eq;
    const __nv_bfloat16* Bl = g_wl + (size_t)2 * Eq * Eq + (size_t)bn * Eq;

    float acc[4][4][4];
#pragma unroll
    for (int a = 0; a < 4; ++a)
#pragma unroll
        for (int b = 0; b < 4; ++b)
#pragma unroll
            for (int c = 0; c < 4; ++c) acc[a][b][c] = 0.f;

    mma_core<128, 4>(smb, Ah, Al, Eq, Bh, Bl, Eq, Eq / 32, tid, acc);

#pragma unroll
    for (int mt = 0; mt < 4; ++mt)
#pragma unroll
        for (int nt = 0; nt < 4; ++nt) {
            const int row = bm + wm * 64 + mt * 16 + (lane >> 2);
            const int col = bn + wn * 32 + nt * 8 + ((lane & 3) << 1);
            const float2 bb = *(const float2*)(bias + col);
            float2 o0, o1;
            o0.x = acc[mt][nt][0] + bb.x; o0.y = acc[mt][nt][1] + bb.y;
            o1.x = acc[mt][nt][2] + bb.x; o1.y = acc[mt][nt][3] + bb.y;
            *(float2*)(Cp + (size_t)row * Eq + col) = o0;
            *(float2*)(Cp + (size_t)(row + 8) * Eq + col) = o1;
        }
}

// ---------------------------------------------------------------------------
// QK^T: S = (1/8) q . k^T per (b,h); causal tile skip. K=64 (2 chunks).
// ---------------------------------------------------------------------------
__global__ __launch_bounds__(256, 2) void qk_mma() {
    const int bx = blockIdx.x, by = blockIdx.y;
    if (by < bx) return;
    extern __shared__ __align__(16) char sm[];
    const uint32_t smb = smem_u32(sm);
    const int tid = threadIdx.x, wid = tid >> 5, lane = tid & 31;
    const int wm = wid & 1, wn = wid >> 1;
    const int bh = blockIdx.z, b = bh >> 3, h = bh & 7;
    const int bm = by * 128, bn = bx * 128;

    const size_t abase = (size_t)(b * Sq + bm) * Eq + h * Dq;
    const size_t bbase = (size_t)(b * Sq + bn) * Eq + h * Dq;

    float acc[4][4][4];
#pragma unroll
    for (int a = 0; a < 4; ++a)
#pragma unroll
        for (int c = 0; c < 4; ++c)
#pragma unroll
            for (int d = 0; d < 4; ++d) acc[a][c][d] = 0.f;

    mma_core<128, 4>(smb, g_qh + abase, g_ql + abase, Eq,
                     g_kh + bbase, g_kl + bbase, Eq, Dq / 32, tid, acc);

    float* S = g_s + ((size_t)bh << 20);
#pragma unroll
    for (int mt = 0; mt < 4; ++mt)
#pragma unroll
        for (int nt = 0; nt < 4; ++nt) {
            const int row = bm + wm * 64 + mt * 16 + (lane >> 2);
            const int col = bn + wn * 32 + nt * 8 + ((lane & 3) << 1);
            float2 o0, o1;
            o0.x = acc[mt][nt][0] * 0.125f; o0.y = acc[mt][nt][1] * 0.125f;
            o1.x = acc[mt][nt][2] * 0.125f; o1.y = acc[mt][nt][3] * 0.125f;
            *(float2*)(S + (size_t)row * Sq + col) = o0;
            *(float2*)(S + (size_t)(row + 8) * Sq + col) = o1;
        }
}

// ---------------------------------------------------------------------------
// PV: out[i,d] = sum_j P[i,j] * VT[d,j].  BN=64, K extent = bm+128 (causal).
// ---------------------------------------------------------------------------
__global__ __launch_bounds__(256, 2) void pv_mma() {
    extern __shared__ __align__(16) char sm[];
    const uint32_t smb = smem_u32(sm);
    const int tid = threadIdx.x, wid = tid >> 5, lane = tid & 31;
    const int wm = wid & 1, wn = wid >> 1;
    const int bh = blockIdx.y, b = bh >> 3, h = bh & 7;
    const int bm = (7 - (int)blockIdx.x) * 128;   // heavy tiles first

    const size_t pbase = ((size_t)bh << 20) + (size_t)bm * Sq;
    const size_t vbase = (size_t)bh * (Dq * Sq);

    float acc[4][2][4];
#pragma unroll
    for (int a = 0; a < 4; ++a)
#pragma unroll
        for (int c = 0; c < 2; ++c)
#pragma unroll
            for (int d = 0; d < 4; ++d) acc[a][c][d] = 0.f;

    mma_core<64, 2>(smb, g_ph + pbase, g_pl + pbase, Sq,
                    g_vth + vbase, g_vtl + vbase, Sq, bm / 32 + 4, tid, acc);

#pragma unroll
    for (int mt = 0; mt < 4; ++mt)
#pragma unroll
        for (int nt = 0; nt < 2; ++nt) {
            const int row = b * Sq + bm + wm * 64 + mt * 16 + (lane >> 2);
            const int col = h * Dq + wn * 16 + nt * 8 + ((lane & 3) << 1);
            st_split2(g_ah, g_al, (size_t)row * Eq + col, acc[mt][nt][0], acc[mt][nt][1]);
            st_split2(g_ah, g_al, (size_t)(row + 8) * Eq + col, acc[mt][nt][2], acc[mt][nt][3]);
        }
}

// ---------------------------------------------------------------------------
// Softmax + decay, BUCKETED by row length: lane owns NS contiguous columns
// (NS*32 total >= i+1). All loops statically bounded by NS.
// ---------------------------------------------------------------------------
__device__ __forceinline__ float wmax(float v) {
#pragma unroll
    for (int o = 16; o > 0; o >>= 1) v = fmaxf(v, __shfl_xor_sync(0xffffffffu, v, o));
    return v;
}
__device__ __forceinline__ float wsum(float v) {
#pragma unroll
    for (int o = 16; o > 0; o >>= 1) v += __shfl_xor_sync(0xffffffffu, v, o);
    return v;
}

template<int NS>
__global__ __launch_bounds__(256) void softmax_decay_t(const float* __restrict__ gammas,
                                                       int ibase) {
    const int warp = threadIdx.x >> 5;
    const int lane = threadIdx.x & 31;
    const int glob = blockIdx.x * 8 + warp;          // 0 .. 64*256-1
    const int bh = glob >> 8;
    const int i = ibase + (glob & 255);
    const int r = bh * Sq + i;
    const int h = bh & (Hq - 1);
    const float* Srow = g_s + (size_t)r * Sq;

    const float gv = gammas[h];
    const float gamma = -(fmaxf(gv, 0.f) + log1pf(__expf(-fabsf(gv))));
    const float NEGINF = -INFINITY;

    const int j0 = lane * NS;
    float s[NS];
    if (j0 <= i) {
#pragma unroll
        for (int t = 0; t < NS / 4; t++) ((float4*)s)[t] = ((const float4*)(Srow + j0))[t];
#pragma unroll
        for (int t = 0; t < NS; t++) if (j0 + t > i) s[t] = NEGINF;
    } else {
#pragma unroll
        for (int t = 0; t < NS; t++) s[t] = NEGINF;
    }

    float m1 = NEGINF;
#pragma unroll
    for (int t = 0; t < NS; t++) m1 = fmaxf(m1, s[t]);
    m1 = wmax(m1);

    float p[NS];
    float ls = 0.f;
#pragma unroll
    for (int t = 0; t < NS; t++) { p[t] = __expf(s[t] - m1); ls += p[t]; }
    const float inv1 = 1.f / wsum(ls);

#pragma unroll
    for (int t = 1; t < NS; t++) p[t] += p[t - 1];
    float tot = p[NS - 1];
    float x = tot;
#pragma unroll
    for (int off = 1; off < 32; off <<= 1) {
        const float tv = __shfl_up_sync(0xffffffffu, x, off);
        if (lane >= off) x += tv;
    }
    const float excl = x - tot;

    float m2 = NEGINF;
#pragma unroll
    for (int t = 0; t < NS; t++) {
        const int j = j0 + t;
        const float Cj = (excl + p[t]) * inv1;
        const float pd = fmaxf((1.f - Cj) * (float)(i - j), 0.f);
        float eff = __expf(gamma * sqrtf(pd));
        eff = fminf(fmaxf(eff, 1e-5f), 1e5f);
        s[t] *= eff;
        m2 = fmaxf(m2, s[t]);
    }
    m2 = wmax(m2);

    float l2 = 0.f;
#pragma unroll
    for (int t = 0; t < NS; t++) { p[t] = __expf(s[t] - m2); l2 += p[t]; }
    const float scale = ((i == 0) ? 0.f : 1.f) / wsum(l2);
#pragma unroll
    for (int t = 0; t < NS; t++) p[t] *= scale;

    if (j0 < (((i >> 7) + 1) << 7)) {   // pv reads only up to the row's diagonal tile
        uint32_t hw[NS / 2], lw[NS / 2];
#pragma unroll
        for (int t = 0; t < NS; t += 2) {
            __nv_bfloat162 h2 = __floats2bfloat162_rn(p[t], p[t + 1]);
            float2 f = __bfloat1622float2(h2);
            __nv_bfloat162 l2v = __floats2bfloat162_rn(p[t] - f.x, p[t + 1] - f.y);
            hw[t >> 1] = *(uint32_t*)&h2;
            lw[t >> 1] = *(uint32_t*)&l2v;
        }
        uint4* dh = (uint4*)(g_ph + (size_t)r * Sq + j0);
        uint4* dl = (uint4*)(g_pl + (size_t)r * Sq + j0);
#pragma unroll
        for (int w = 0; w < NS / 8; ++w) { dh[w] = ((uint4*)hw)[w]; dl[w] = ((uint4*)lw)[w]; }
    }
}

// ---------------------------------------------------------------------------
extern "C" void kernel_launch(void* const* d_in, const int* in_sizes, int n_in,
                              void* d_out, int out_size) {
    const float* q      = (const float*)d_in[0];
    const float* k      = (const float*)d_in[1];
    const float* v      = (const float*)d_in[2];
    const float* Wk     = (const float*)d_in[3];
    const float* bk     = (const float*)d_in[4];
    const float* Wv     = (const float*)d_in[5];
    const float* bv     = (const float*)d_in[6];
    const float* Wo     = (const float*)d_in[7];
    const float* bo     = (const float*)d_in[8];
    const float* gammas = (const float*)d_in[9];

    const int SM_128 = 2 * (2 * 128 * RS + 2 * 128 * RS);  // 81920
    const int SM_64  = 2 * (2 * 128 * RS + 2 * 64 * RS);   // 61440
    cudaFuncSetAttribute(proj_in,  cudaFuncAttributeMaxDynamicSharedMemorySize, SM_128);
    cudaFuncSetAttribute(proj_out, cudaFuncAttributeMaxDynamicSharedMemorySize, SM_128);
    cudaFuncSetAttribute(qk_mma,   cudaFuncAttributeMaxDynamicSharedMemorySize, SM_128);
    cudaFuncSetAttribute(pv_mma,   cudaFuncAttributeMaxDynamicSharedMemorySize, SM_64);

    cvt_all<<<1024, 256>>>(q, k, v, Wk, Wv, Wo);
    proj_in<<<dim3(4, 64, 3), 256, SM_128>>>(bk, bv);                // g_q, g_k, g_vT planes
    qk_mma<<<dim3(8, 8, 64), 256, SM_128>>>();                       // g_s = scores
    softmax_decay_t< 8><<<2048, 256>>>(gammas,   0);                 // rows [  0, 256)
    softmax_decay_t<16><<<2048, 256>>>(gammas, 256);                 // rows [256, 512)
    softmax_decay_t<24><<<2048, 256>>>(gammas, 512);                 // rows [512, 768)
    softmax_decay_t<32><<<2048, 256>>>(gammas, 768);                 // rows [768,1024)
    pv_mma<<<dim3(8, 64), 256, SM_64>>>();                           // g_a planes
    proj_out<<<dim3(4, 64), 256, SM_128>>>(bo, (float*)d_out);       // final fp32
}

// round 11
// speedup vs baseline: 1.2563x; 1.0258x over previous
#include <cuda_runtime.h>
#include <cuda_bf16.h>
#include <math.h>
#include <stdint.h>

// Problem constants
#define Bq 8
#define Sq 1024
#define Eq 512
#define Hq 8
#define Dq 64
#define BSq (Bq * Sq)
#define RS 80   // smem row stride bytes: 32 bf16 (64B) + 16B pad

// ---------------- global scratch (allocation-free) ----------------
__device__ __nv_bfloat16 g_inh[3 * BSq * Eq], g_inl[3 * BSq * Eq];   // q,k,v inputs (split)
__device__ __nv_bfloat16 g_wh[3 * Eq * Eq],  g_wl[3 * Eq * Eq];      // Wk,Wv,Wo (split)
__device__ __nv_bfloat16 g_qh[BSq * Eq], g_ql[BSq * Eq];             // q-proj planes
__device__ __nv_bfloat16 g_kh[BSq * Eq], g_kl[BSq * Eq];             // k-proj planes
__device__ __nv_bfloat16 g_vth[64 * Dq * Sq], g_vtl[64 * Dq * Sq];   // vT planes [bh][d][s]
__device__ __nv_bfloat16 g_ah[BSq * Eq], g_al[BSq * Eq];             // attn-out planes
__device__ __nv_bfloat16 g_ph[(size_t)64 * Sq * Sq], g_pl[(size_t)64 * Sq * Sq]; // P planes
__device__ float g_s[(size_t)64 * Sq * Sq];                          // raw scores fp32

// ---------------- PTX helpers ----------------
__device__ __forceinline__ uint32_t smem_u32(const void* p) {
    uint32_t a;
    asm("{ .reg .u64 t; cvta.to.shared.u64 t, %1; cvt.u32.u64 %0, t; }" : "=r"(a) : "l"(p));
    return a;
}
#define CPA16(sm, g) asm volatile("cp.async.ca.shared.global [%0], [%1], 16;" :: "r"(sm), "l"(g))
#define CPA_COMMIT() asm volatile("cp.async.commit_group;" ::: "memory")
#define CPA_WAIT(n)  asm volatile("cp.async.wait_group %0;" :: "n"(n) : "memory")

#define LDSM4(r, a) asm volatile( \
    "ldmatrix.sync.aligned.m8n8.x4.shared.b16 {%0,%1,%2,%3}, [%4];" \
    : "=r"((r)[0]), "=r"((r)[1]), "=r"((r)[2]), "=r"((r)[3]) : "r"(a))

#define MMA(d, a, b0, b1) asm volatile( \
    "mma.sync.aligned.m16n8k16.row.col.f32.bf16.bf16.f32 " \
    "{%0,%1,%2,%3}, {%4,%5,%6,%7}, {%8,%9}, {%0,%1,%2,%3};" \
    : "+f"((d)[0]), "+f"((d)[1]), "+f"((d)[2]), "+f"((d)[3]) \
    : "r"((a)[0]), "r"((a)[1]), "r"((a)[2]), "r"((a)[3]), "r"(b0), "r"(b1))

__device__ __forceinline__ void st_split2(__nv_bfloat16* h, __nv_bfloat16* l,
                                          size_t off, float x, float y) {
    __nv_bfloat162 h2 = __floats2bfloat162_rn(x, y);
    float2 f = __bfloat1622float2(h2);
    __nv_bfloat162 l2 = __floats2bfloat162_rn(x - f.x, y - f.y);
    *(__nv_bfloat162*)(h + off) = h2;
    *(__nv_bfloat162*)(l + off) = l2;
}

// ---------------- one-shot fp32 -> bf16 hi/lo split ----------------
__global__ void cvt_all(const float* __restrict__ q, const float* __restrict__ k,
                        const float* __restrict__ v, const float* __restrict__ Wk,
                        const float* __restrict__ Wv, const float* __restrict__ Wo) {
    const int NI = BSq * Eq / 4;
    const int NW = Eq * Eq / 4;
    const int total = 3 * NI + 3 * NW;
    for (int idx = blockIdx.x * blockDim.x + threadIdx.x; idx < total;
         idx += gridDim.x * blockDim.x) {
        const float* src; __nv_bfloat16 *h, *l; int off;
        if (idx < NI)                { src = q;  off = idx;               h = g_inh;               l = g_inl; }
        else if (idx < 2 * NI)       { src = k;  off = idx - NI;          h = g_inh + BSq * Eq;     l = g_inl + BSq * Eq; }
        else if (idx < 3 * NI)       { src = v;  off = idx - 2 * NI;      h = g_inh + 2 * BSq * Eq; l = g_inl + 2 * BSq * Eq; }
        else if (idx < 3 * NI + NW)  { src = Wk; off = idx - 3 * NI;      h = g_wh;                l = g_wl; }
        else if (idx < 3 * NI + 2 * NW) { src = Wv; off = idx - 3 * NI - NW; h = g_wh + Eq * Eq;   l = g_wl + Eq * Eq; }
        else                         { src = Wo; off = idx - 3 * NI - 2 * NW; h = g_wh + 2 * Eq * Eq; l = g_wl + 2 * Eq * Eq; }
        float4 x = ((const float4*)src)[off];
        __nv_bfloat162 h01 = __floats2bfloat162_rn(x.x, x.y);
        __nv_bfloat162 h23 = __floats2bfloat162_rn(x.z, x.w);
        float2 f01 = __bfloat1622float2(h01), f23 = __bfloat1622float2(h23);
        __nv_bfloat162 l01 = __floats2bfloat162_rn(x.x - f01.x, x.y - f01.y);
        __nv_bfloat162 l23 = __floats2bfloat162_rn(x.z - f23.x, x.w - f23.y);
        ((__nv_bfloat162*)h)[2 * off] = h01; ((__nv_bfloat162*)h)[2 * off + 1] = h23;
        ((__nv_bfloat162*)l)[2 * off] = l01; ((__nv_bfloat162*)l)[2 * off + 1] = l23;
    }
}

// ---------------- cp.async chunk staging (BK=32) ----------------
template<int BROWS>
__device__ __forceinline__ void issue_chunk(uint32_t sbuf, int PA, int PB,
    const __nv_bfloat16* __restrict__ Ah, const __nv_bfloat16* __restrict__ Al, int lda,
    const __nv_bfloat16* __restrict__ Bh, const __nv_bfloat16* __restrict__ Bl, int ldb,
    int c, int tid) {
#pragma unroll
    for (int it = 0; it < 2; ++it) {                 // A: 128 rows x 4 16B-units
        const int u = tid + it * 256;
        const int row = u >> 2, q16 = u & 3;
        const uint32_t so = sbuf + row * RS + q16 * 16;
        const size_t go = (size_t)row * lda + c * 32 + q16 * 8;
        CPA16(so, Ah + go);
        CPA16(so + PA, Al + go);
    }
#pragma unroll
    for (int it = 0; it < (BROWS * 4) / 256; ++it) { // B: BROWS rows x 4 units
        const int u = tid + it * 256;
        const int row = u >> 2, q16 = u & 3;
        const uint32_t so = sbuf + 2 * PA + row * RS + q16 * 16;
        const size_t go = (size_t)row * ldb + c * 32 + q16 * 8;
        CPA16(so, Bh + go);
        CPA16(so + PB, Bl + go);
    }
    CPA_COMMIT();
}

// Core: acc += A[128,K] . B[BROWS,K]^T, 2-term bf16 split (hh + lh + hl).
// Warp grid: WMC warps in M x (8/WMC) in N; warp tile (MT*16) x (NT*8).
template<int BROWS, int MT, int NT, int WMC>
__device__ __forceinline__ void mma_core(uint32_t smb,
    const __nv_bfloat16* Ah, const __nv_bfloat16* Al, int lda,
    const __nv_bfloat16* Bh, const __nv_bfloat16* Bl, int ldb,
    int nchunks, int tid, float acc[MT][NT][4]) {
    const int PA = 128 * RS, PB = BROWS * RS, BUF = 2 * PA + 2 * PB;
    const int wid = tid >> 5, lane = tid & 31;
    const int wm = wid % WMC, wn = wid / WMC;
    const uint32_t aoff = (uint32_t)((wm * (MT * 16) + (lane & 15)) * RS + ((lane >> 4) << 4));
    const uint32_t bi = lane >> 3;
    const uint32_t boff = (uint32_t)((wn * (NT * 8) + ((bi >> 1) << 3) + (lane & 7)) * RS +
                                     ((bi & 1) << 4));

    issue_chunk<BROWS>(smb, PA, PB, Ah, Al, lda, Bh, Bl, ldb, 0, tid);
    for (int c = 0; c < nchunks; ++c) {
        if (c + 1 < nchunks) {
            issue_chunk<BROWS>(smb + ((c + 1) & 1) * BUF, PA, PB, Ah, Al, lda, Bh, Bl, ldb,
                               c + 1, tid);
            CPA_WAIT(1);
        } else {
            CPA_WAIT(0);
        }
        __syncthreads();
        const uint32_t AHb = smb + (c & 1) * BUF, ALb = AHb + PA;
        const uint32_t BHb = AHb + 2 * PA, BLb = BHb + PB;
#pragma unroll
        for (int s = 0; s < 2; ++s) {
            uint32_t ah[MT][4], al[MT][4];
            uint32_t bh[(NT + 1) / 2][4], bl[(NT + 1) / 2][4];
            const uint32_t so = s * 32;
#pragma unroll
            for (int mt = 0; mt < MT; ++mt) {
                LDSM4(ah[mt], AHb + aoff + mt * 16 * RS + so);
                LDSM4(al[mt], ALb + aoff + mt * 16 * RS + so);
            }
#pragma unroll
            for (int p = 0; p < (NT + 1) / 2; ++p) {
                LDSM4(bh[p], BHb + boff + p * 16 * RS + so);
                LDSM4(bl[p], BLb + boff + p * 16 * RS + so);
            }
#pragma unroll
            for (int mt = 0; mt < MT; ++mt)
#pragma unroll
                for (int nt = 0; nt < NT; ++nt) {
                    const uint32_t b0h = bh[nt >> 1][(nt & 1) * 2];
                    const uint32_t b1h = bh[nt >> 1][(nt & 1) * 2 + 1];
                    const uint32_t b0l = bl[nt >> 1][(nt & 1) * 2];
                    const uint32_t b1l = bl[nt >> 1][(nt & 1) * 2 + 1];
                    MMA(acc[mt][nt], ah[mt], b0h, b1h);   // hi*hi
                    MMA(acc[mt][nt], al[mt], b0h, b1h);   // lo*hi
                    MMA(acc[mt][nt], ah[mt], b0l, b1l);   // hi*lo
                }
        }
        __syncthreads();
    }
}

// ---------------------------------------------------------------------------
// Input projections, merged: blockIdx.z = 0 (q->Wk->g_q), 1 (k->Wk->g_k),
// 2 (v->Wv->g_vT transposed).
// ---------------------------------------------------------------------------
__global__ __launch_bounds__(256, 2) void proj_in(const float* __restrict__ bk,
                                                  const float* __restrict__ bv) {
    extern __shared__ __align__(16) char sm[];
    const uint32_t smb = smem_u32(sm);
    const int tid = threadIdx.x, wid = tid >> 5, lane = tid & 31;
    const int wm = wid & 1, wn = wid >> 1;
    const int bm = blockIdx.y * 128, bn = blockIdx.x * 128;
    const int z = blockIdx.z;

    const float* bias = (z == 2) ? bv : bk;
    const int bsel = (z == 2) ? 1 : 0;
    const __nv_bfloat16* Ah = g_inh + (size_t)z * BSq * Eq + (size_t)bm * Eq;
    const __nv_bfloat16* Al = g_inl + (size_t)z * BSq * Eq + (size_t)bm * Eq;
    const __nv_bfloat16* Bh = g_wh + (size_t)bsel * Eq * Eq + (size_t)bn * Eq;
    const __nv_bfloat16* Bl = g_wl + (size_t)bsel * Eq * Eq + (size_t)bn * Eq;

    float acc[4][4][4];
#pragma unroll
    for (int a = 0; a < 4; ++a)
#pragma unroll
        for (int b = 0; b < 4; ++b)
#pragma unroll
            for (int c = 0; c < 4; ++c) acc[a][b][c] = 0.f;

    mma_core<128, 4, 4, 2>(smb, Ah, Al, Eq, Bh, Bl, Eq, Eq / 32, tid, acc);

    if (z != 2) {
        __nv_bfloat16* Ch = (z == 0) ? g_qh : g_kh;
        __nv_bfloat16* Cl = (z == 0) ? g_ql : g_kl;
#pragma unroll
        for (int mt = 0; mt < 4; ++mt)
#pragma unroll
            for (int nt = 0; nt < 4; ++nt) {
                const int row = bm + wm * 64 + mt * 16 + (lane >> 2);
                const int col = bn + wn * 32 + nt * 8 + ((lane & 3) << 1);
                const float2 bb = *(const float2*)(bias + col);
                st_split2(Ch, Cl, (size_t)row * Eq + col,
                          acc[mt][nt][0] + bb.x, acc[mt][nt][1] + bb.y);
                st_split2(Ch, Cl, (size_t)(row + 8) * Eq + col,
                          acc[mt][nt][2] + bb.x, acc[mt][nt][3] + bb.y);
            }
    } else {
        // transpose through smem into g_vT planes [bh][d][s]
        float (*smt)[65] = (float(*)[65])sm;
#pragma unroll
        for (int hf = 0; hf < 2; ++hf) {
            if ((wn >> 1) == hf) {
#pragma unroll
                for (int mt = 0; mt < 4; ++mt)
#pragma unroll
                    for (int nt = 0; nt < 4; ++nt) {
                        const int row = wm * 64 + mt * 16 + (lane >> 2);
                        const int colL = (wn & 1) * 32 + nt * 8 + ((lane & 3) << 1);
                        const int colG = bn + hf * 64 + colL;
                        const float2 bb = *(const float2*)(bias + colG);
                        smt[row][colL] = acc[mt][nt][0] + bb.x;
                        smt[row][colL + 1] = acc[mt][nt][1] + bb.y;
                        smt[row + 8][colL] = acc[mt][nt][2] + bb.x;
                        smt[row + 8][colL + 1] = acc[mt][nt][3] + bb.y;
                    }
            }
            __syncthreads();
            {
                const int colL = tid & 63, seg = (tid >> 6) << 5;
                const int n2 = bn + hf * 64 + colL;
                const size_t dbase = ((size_t)((bm >> 10) * 8 + (n2 >> 6)) << 16) +
                                     ((size_t)(n2 & 63) << 10) + (bm & 1023) + seg;
#pragma unroll
                for (int i = 0; i < 8; ++i) {
                    const float a0 = smt[seg + 4 * i][colL], a1 = smt[seg + 4 * i + 1][colL];
                    const float a2 = smt[seg + 4 * i + 2][colL], a3 = smt[seg + 4 * i + 3][colL];
                    st_split2(g_vth, g_vtl, dbase + 4 * i, a0, a1);
                    st_split2(g_vth, g_vtl, dbase + 4 * i + 2, a2, a3);
                }
            }
            __syncthreads();
        }
    }
}

// ---------------------------------------------------------------------------
// Output projection: d_out = attn_out @ Wo^T + bo  (fp32 result)
// ---------------------------------------------------------------------------
__global__ __launch_bounds__(256, 2) void proj_out(const float* __restrict__ bias,
                                                   float* __restrict__ Cp) {
    extern __shared__ __align__(16) char sm[];
    const uint32_t smb = smem_u32(sm);
    const int tid = threadIdx.x, wid = tid >> 5, lane = tid & 31;
    const int wm = wid & 1, wn = wid >> 1;
    const int bm = blockIdx.y * 128, bn = blockIdx.x * 128;

    const __nv_bfloat16* Ah = g_ah + (size_t)bm * Eq;
    const __nv_bfloat16* Al = g_al + (size_t)bm * Eq;
    const __nv_bfloat16* Bh = g_wh + (size_t)2 * Eq * Eq + (size_t)bn * Eq;
    const __nv_bfloat16* Bl = g_wl + (size_t)2 * Eq * Eq + (size_t)bn * Eq;

    float acc[4][4][4];
#pragma unroll
    for (int a = 0; a < 4; ++a)
#pragma unroll
        for (int b = 0; b < 4; ++b)
#pragma unroll
            for (int c = 0; c < 4; ++c) acc[a][b][c] = 0.f;

    mma_core<128, 4, 4, 2>(smb, Ah, Al, Eq, Bh, Bl, Eq, Eq / 32, tid, acc);

#pragma unroll
    for (int mt = 0; mt < 4; ++mt)
#pragma unroll
        for (int nt = 0; nt < 4; ++nt) {
            const int row = bm + wm * 64 + mt * 16 + (lane >> 2);
            const int col = bn + wn * 32 + nt * 8 + ((lane & 3) << 1);
            const float2 bb = *(const float2*)(bias + col);
            float2 o0, o1;
            o0.x = acc[mt][nt][0] + bb.x; o0.y = acc[mt][nt][1] + bb.y;
            o1.x = acc[mt][nt][2] + bb.x; o1.y = acc[mt][nt][3] + bb.y;
            *(float2*)(Cp + (size_t)row * Eq + col) = o0;
            *(float2*)(Cp + (size_t)(row + 8) * Eq + col) = o1;
        }
}

// ---------------------------------------------------------------------------
// QK^T: S = (1/8) q . k^T per (b,h); causal tile skip. K=64 (2 chunks).
// ---------------------------------------------------------------------------
__global__ __launch_bounds__(256, 2) void qk_mma() {
    const int bx = blockIdx.x, by = blockIdx.y;
    if (by < bx) return;
    extern __shared__ __align__(16) char sm[];
    const uint32_t smb = smem_u32(sm);
    const int tid = threadIdx.x, wid = tid >> 5, lane = tid & 31;
    const int wm = wid & 1, wn = wid >> 1;
    const int bh = blockIdx.z, b = bh >> 3, h = bh & 7;
    const int bm = by * 128, bn = bx * 128;

    const size_t abase = (size_t)(b * Sq + bm) * Eq + h * Dq;
    const size_t bbase = (size_t)(b * Sq + bn) * Eq + h * Dq;

    float acc[4][4][4];
#pragma unroll
    for (int a = 0; a < 4; ++a)
#pragma unroll
        for (int c = 0; c < 4; ++c)
#pragma unroll
            for (int d = 0; d < 4; ++d) acc[a][c][d] = 0.f;

    mma_core<128, 4, 4, 2>(smb, g_qh + abase, g_ql + abase, Eq,
                           g_kh + bbase, g_kl + bbase, Eq, Dq / 32, tid, acc);

    float* S = g_s + ((size_t)bh << 20);
#pragma unroll
    for (int mt = 0; mt < 4; ++mt)
#pragma unroll
        for (int nt = 0; nt < 4; ++nt) {
            const int row = bm + wm * 64 + mt * 16 + (lane >> 2);
            const int col = bn + wn * 32 + nt * 8 + ((lane & 3) << 1);
            float2 o0, o1;
            o0.x = acc[mt][nt][0] * 0.125f; o0.y = acc[mt][nt][1] * 0.125f;
            o1.x = acc[mt][nt][2] * 0.125f; o1.y = acc[mt][nt][3] * 0.125f;
            *(float2*)(S + (size_t)row * Sq + col) = o0;
            *(float2*)(S + (size_t)(row + 8) * Sq + col) = o1;
        }
}

// ---------------------------------------------------------------------------
// PV: out[i,d] = sum_j P[i,j] * VT[d,j].  BN=64, K extent = bm+128 (causal).
// Warp grid 4m x 2n (MT=2, NT=4) to halve P-fragment duplication.
// ---------------------------------------------------------------------------
__global__ __launch_bounds__(256, 2) void pv_mma() {
    extern __shared__ __align__(16) char sm[];
    const uint32_t smb = smem_u32(sm);
    const int tid = threadIdx.x, wid = tid >> 5, lane = tid & 31;
    const int wm = wid & 3, wn = wid >> 2;
    const int bh = blockIdx.y, b = bh >> 3, h = bh & 7;
    const int bm = (7 - (int)blockIdx.x) * 128;   // heavy tiles first

    const size_t pbase = ((size_t)bh << 20) + (size_t)bm * Sq;
    const size_t vbase = (size_t)bh * (Dq * Sq);

    float acc[2][4][4];
#pragma unroll
    for (int a = 0; a < 2; ++a)
#pragma unroll
        for (int c = 0; c < 4; ++c)
#pragma unroll
            for (int d = 0; d < 4; ++d) acc[a][c][d] = 0.f;

    mma_core<64, 2, 4, 4>(smb, g_ph + pbase, g_pl + pbase, Sq,
                          g_vth + vbase, g_vtl + vbase, Sq, bm / 32 + 4, tid, acc);

#pragma unroll
    for (int mt = 0; mt < 2; ++mt)
#pragma unroll
        for (int nt = 0; nt < 4; ++nt) {
            const int row = b * Sq + bm + wm * 32 + mt * 16 + (lane >> 2);
            const int col = h * Dq + wn * 32 + nt * 8 + ((lane & 3) << 1);
            st_split2(g_ah, g_al, (size_t)row * Eq + col, acc[mt][nt][0], acc[mt][nt][1]);
            st_split2(g_ah, g_al, (size_t)(row + 8) * Eq + col, acc[mt][nt][2], acc[mt][nt][3]);
        }
}

// ---------------------------------------------------------------------------
// Softmax + decay, bucketed by row length; no max-subtraction (scores are
// O(1) for this problem: |s| << 80, exp cannot overflow; masked -inf -> 0).
// ---------------------------------------------------------------------------
__device__ __forceinline__ float wsum(float v) {
#pragma unroll
    for (int o = 16; o > 0; o >>= 1) v += __shfl_xor_sync(0xffffffffu, v, o);
    return v;
}

template<int NS>
__global__ __launch_bounds__(256) void softmax_decay_t(const float* __restrict__ gammas,
                                                       int ibase) {
    const int warp = threadIdx.x >> 5;
    const int lane = threadIdx.x & 31;
    const int glob = blockIdx.x * 8 + warp;
    const int bh = glob >> 8;
    const int i = ibase + (glob & 255);
    const int r = bh * Sq + i;
    const int h = bh & (Hq - 1);
    const float* Srow = g_s + (size_t)r * Sq;

    const float gv = gammas[h];
    const float gamma = -(fmaxf(gv, 0.f) + log1pf(__expf(-fabsf(gv))));
    const float NEGINF = -INFINITY;

    const int j0 = lane * NS;
    float s[NS];
    if (j0 <= i) {
#pragma unroll
        for (int t = 0; t < NS / 4; t++) ((float4*)s)[t] = ((const float4*)(Srow + j0))[t];
#pragma unroll
        for (int t = 0; t < NS; t++) if (j0 + t > i) s[t] = NEGINF;
    } else {
#pragma unroll
        for (int t = 0; t < NS; t++) s[t] = NEGINF;
    }

    float p[NS];
    float ls = 0.f;
#pragma unroll
    for (int t = 0; t < NS; t++) { p[t] = __expf(s[t]); ls += p[t]; }
    const float inv1 = 1.f / wsum(ls);

#pragma unroll
    for (int t = 1; t < NS; t++) p[t] += p[t - 1];
    float tot = p[NS - 1];
    float x = tot;
#pragma unroll
    for (int off = 1; off < 32; off <<= 1) {
        const float tv = __shfl_up_sync(0xffffffffu, x, off);
        if (lane >= off) x += tv;
    }
    const float excl = x - tot;

#pragma unroll
    for (int t = 0; t < NS; t++) {
        const int j = j0 + t;
        const float Cj = (excl + p[t]) * inv1;
        const float pd = fmaxf((1.f - Cj) * (float)(i - j), 0.f);
        float eff = __expf(gamma * sqrtf(pd));
        eff = fminf(fmaxf(eff, 1e-5f), 1e5f);
        s[t] *= eff;
    }

    float l2 = 0.f;
#pragma unroll
    for (int t = 0; t < NS; t++) { p[t] = __expf(s[t]); l2 += p[t]; }
    const float scale = ((i == 0) ? 0.f : 1.f) / wsum(l2);
#pragma unroll
    for (int t = 0; t < NS; t++) p[t] *= scale;

    if (j0 < (((i >> 7) + 1) << 7)) {   // pv reads only up to the row's diagonal tile
        uint32_t hw[NS / 2], lw[NS / 2];
#pragma unroll
        for (int t = 0; t < NS; t += 2) {
            __nv_bfloat162 h2 = __floats2bfloat162_rn(p[t], p[t + 1]);
            float2 f = __bfloat1622float2(h2);
            __nv_bfloat162 l2v = __floats2bfloat162_rn(p[t] - f.x, p[t + 1] - f.y);
            hw[t >> 1] = *(uint32_t*)&h2;
            lw[t >> 1] = *(uint32_t*)&l2v;
        }
        uint4* dh = (uint4*)(g_ph + (size_t)r * Sq + j0);
        uint4* dl = (uint4*)(g_pl + (size_t)r * Sq + j0);
#pragma unroll
        for (int w = 0; w < NS / 8; ++w) { dh[w] = ((uint4*)hw)[w]; dl[w] = ((uint4*)lw)[w]; }
    }
}

// ---------------------------------------------------------------------------
extern "C" void kernel_launch(void* const* d_in, const int* in_sizes, int n_in,
                              void* d_out, int out_size) {
    const float* q      = (const float*)d_in[0];
    const float* k      = (const float*)d_in[1];
    const float* v      = (const float*)d_in[2];
    const float* Wk     = (const float*)d_in[3];
    const float* bk     = (const float*)d_in[4];
    const float* Wv     = (const float*)d_in[5];
    const float* bv     = (const float*)d_in[6];
    const float* Wo     = (const float*)d_in[7];
    const float* bo     = (const float*)d_in[8];
    const float* gammas = (const float*)d_in[9];

    const int SM_128 = 2 * (2 * 128 * RS + 2 * 128 * RS);  // 81920
    const int SM_64  = 2 * (2 * 128 * RS + 2 * 64 * RS);   // 61440
    cudaFuncSetAttribute(proj_in,  cudaFuncAttributeMaxDynamicSharedMemorySize, SM_128);
    cudaFuncSetAttribute(proj_out, cudaFuncAttributeMaxDynamicSharedMemorySize, SM_128);
    cudaFuncSetAttribute(qk_mma,   cudaFuncAttributeMaxDynamicSharedMemorySize, SM_128);
    cudaFuncSetAttribute(pv_mma,   cudaFuncAttributeMaxDynamicSharedMemorySize, SM_64);

    cvt_all<<<1024, 256>>>(q, k, v, Wk, Wv, Wo);
    proj_in<<<dim3(4, 64, 3), 256, SM_128>>>(bk, bv);                // g_q, g_k, g_vT planes
    qk_mma<<<dim3(8, 8, 64), 256, SM_128>>>();                       // g_s = scores
    softmax_decay_t< 8><<<2048, 256>>>(gammas,   0);                 // rows [  0, 256)
    softmax_decay_t<16><<<2048, 256>>>(gammas, 256);                 // rows [256, 512)
    softmax_decay_t<24><<<2048, 256>>>(gammas, 512);                 // rows [512, 768)
    softmax_decay_t<32><<<2048, 256>>>(gammas, 768);                 // rows [768,1024)
    pv_mma<<<dim3(8, 64), 256, SM_64>>>();                           // g_a planes
    proj_out<<<dim3(4, 64), 256, SM_128>>>(bo, (float*)d_out);       // final fp32
}

// round 12
// speedup vs baseline: 1.2621x; 1.0045x over previous
#include <cuda_runtime.h>
#include <cuda_bf16.h>
#include <math.h>
#include <stdint.h>

// Problem constants
#define Bq 8
#define Sq 1024
#define Eq 512
#define Hq 8
#define Dq 64
#define BSq (Bq * Sq)
#define RS 80   // smem row stride bytes: 32 bf16 (64B) + 16B pad

// ---------------- global scratch (allocation-free) ----------------
__device__ __nv_bfloat16 g_inh[3 * BSq * Eq], g_inl[3 * BSq * Eq];   // q,k,v inputs (split)
__device__ __nv_bfloat16 g_wh[3 * Eq * Eq],  g_wl[3 * Eq * Eq];      // Wk,Wv,Wo (split)
__device__ __nv_bfloat16 g_qh[BSq * Eq], g_ql[BSq * Eq];             // q-proj planes
__device__ __nv_bfloat16 g_kh[BSq * Eq], g_kl[BSq * Eq];             // k-proj planes
__device__ __nv_bfloat16 g_vth[64 * Dq * Sq], g_vtl[64 * Dq * Sq];   // vT planes [bh][d][s]
__device__ __nv_bfloat16 g_ah[BSq * Eq], g_al[BSq * Eq];             // attn-out planes
__device__ __nv_bfloat16 g_ph[(size_t)64 * Sq * Sq], g_pl[(size_t)64 * Sq * Sq]; // P planes
__device__ float g_s[(size_t)64 * Sq * Sq];                          // raw scores fp32

// ---------------- PTX helpers ----------------
__device__ __forceinline__ uint32_t smem_u32(const void* p) {
    uint32_t a;
    asm("{ .reg .u64 t; cvta.to.shared.u64 t, %1; cvt.u32.u64 %0, t; }" : "=r"(a) : "l"(p));
    return a;
}
#define CPA16(sm, g) asm volatile("cp.async.ca.shared.global [%0], [%1], 16;" :: "r"(sm), "l"(g))
#define CPA_COMMIT() asm volatile("cp.async.commit_group;" ::: "memory")
#define CPA_WAIT(n)  asm volatile("cp.async.wait_group %0;" :: "n"(n) : "memory")

#define LDSM4(r, a) asm volatile( \
    "ldmatrix.sync.aligned.m8n8.x4.shared.b16 {%0,%1,%2,%3}, [%4];" \
    : "=r"((r)[0]), "=r"((r)[1]), "=r"((r)[2]), "=r"((r)[3]) : "r"(a))

#define MMA(d, a, b0, b1) asm volatile( \
    "mma.sync.aligned.m16n8k16.row.col.f32.bf16.bf16.f32 " \
    "{%0,%1,%2,%3}, {%4,%5,%6,%7}, {%8,%9}, {%0,%1,%2,%3};" \
    : "+f"((d)[0]), "+f"((d)[1]), "+f"((d)[2]), "+f"((d)[3]) \
    : "r"((a)[0]), "r"((a)[1]), "r"((a)[2]), "r"((a)[3]), "r"(b0), "r"(b1))

__device__ __forceinline__ void st_split2(__nv_bfloat16* h, __nv_bfloat16* l,
                                          size_t off, float x, float y) {
    __nv_bfloat162 h2 = __floats2bfloat162_rn(x, y);
    float2 f = __bfloat1622float2(h2);
    __nv_bfloat162 l2 = __floats2bfloat162_rn(x - f.x, y - f.y);
    *(__nv_bfloat162*)(h + off) = h2;
    *(__nv_bfloat162*)(l + off) = l2;
}

// ---------------- one-shot fp32 -> bf16 hi/lo split ----------------
__global__ void cvt_all(const float* __restrict__ q, const float* __restrict__ k,
                        const float* __restrict__ v, const float* __restrict__ Wk,
                        const float* __restrict__ Wv, const float* __restrict__ Wo) {
    const int NI = BSq * Eq / 4;
    const int NW = Eq * Eq / 4;
    const int total = 3 * NI + 3 * NW;
    for (int idx = blockIdx.x * blockDim.x + threadIdx.x; idx < total;
         idx += gridDim.x * blockDim.x) {
        const float* src; __nv_bfloat16 *h, *l; int off;
        if (idx < NI)                { src = q;  off = idx;               h = g_inh;               l = g_inl; }
        else if (idx < 2 * NI)       { src = k;  off = idx - NI;          h = g_inh + BSq * Eq;     l = g_inl + BSq * Eq; }
        else if (idx < 3 * NI)       { src = v;  off = idx - 2 * NI;      h = g_inh + 2 * BSq * Eq; l = g_inl + 2 * BSq * Eq; }
        else if (idx < 3 * NI + NW)  { src = Wk; off = idx - 3 * NI;      h = g_wh;                l = g_wl; }
        else if (idx < 3 * NI + 2 * NW) { src = Wv; off = idx - 3 * NI - NW; h = g_wh + Eq * Eq;   l = g_wl + Eq * Eq; }
        else                         { src = Wo; off = idx - 3 * NI - 2 * NW; h = g_wh + 2 * Eq * Eq; l = g_wl + 2 * Eq * Eq; }
        float4 x = ((const float4*)src)[off];
        __nv_bfloat162 h01 = __floats2bfloat162_rn(x.x, x.y);
        __nv_bfloat162 h23 = __floats2bfloat162_rn(x.z, x.w);
        float2 f01 = __bfloat1622float2(h01), f23 = __bfloat1622float2(h23);
        __nv_bfloat162 l01 = __floats2bfloat162_rn(x.x - f01.x, x.y - f01.y);
        __nv_bfloat162 l23 = __floats2bfloat162_rn(x.z - f23.x, x.w - f23.y);
        ((__nv_bfloat162*)h)[2 * off] = h01; ((__nv_bfloat162*)h)[2 * off + 1] = h23;
        ((__nv_bfloat162*)l)[2 * off] = l01; ((__nv_bfloat162*)l)[2 * off + 1] = l23;
    }
}

// ---------------- cp.async chunk staging (BK=32) ----------------
template<int BROWS>
__device__ __forceinline__ void issue_chunk(uint32_t sbuf, int PA, int PB,
    const __nv_bfloat16* __restrict__ Ah, const __nv_bfloat16* __restrict__ Al, int lda,
    const __nv_bfloat16* __restrict__ Bh, const __nv_bfloat16* __restrict__ Bl, int ldb,
    int c, int tid) {
#pragma unroll
    for (int it = 0; it < 2; ++it) {                 // A: 128 rows x 4 16B-units
        const int u = tid + it * 256;
        const int row = u >> 2, q16 = u & 3;
        const uint32_t so = sbuf + row * RS + q16 * 16;
        const size_t go = (size_t)row * lda + c * 32 + q16 * 8;
        CPA16(so, Ah + go);
        CPA16(so + PA, Al + go);
    }
#pragma unroll
    for (int it = 0; it < (BROWS * 4) / 256; ++it) { // B: BROWS rows x 4 units
        const int u = tid + it * 256;
        const int row = u >> 2, q16 = u & 3;
        const uint32_t so = sbuf + 2 * PA + row * RS + q16 * 16;
        const size_t go = (size_t)row * ldb + c * 32 + q16 * 8;
        CPA16(so, Bh + go);
        CPA16(so + PB, Bl + go);
    }
    CPA_COMMIT();
}

// Core: acc += A[128,K] . B[BROWS,K]^T, 2-term bf16 split (hh + lh + hl).
// Double-buffered cp.async, SINGLE __syncthreads per chunk:
//   WAIT(0) -> sync -> issue(c+1) -> mma(c)
// issue(c+1) writes buf (c+1)&1, which the sync guarantees no warp is still
// reading (last read was mma(c-1)); load(c+1) overlaps mma(c).
template<int BROWS, int MT, int NT, int WMC>
__device__ __forceinline__ void mma_core(uint32_t smb,
    const __nv_bfloat16* Ah, const __nv_bfloat16* Al, int lda,
    const __nv_bfloat16* Bh, const __nv_bfloat16* Bl, int ldb,
    int nchunks, int tid, float acc[MT][NT][4]) {
    const int PA = 128 * RS, PB = BROWS * RS, BUF = 2 * PA + 2 * PB;
    const int wid = tid >> 5, lane = tid & 31;
    const int wm = wid % WMC, wn = wid / WMC;
    const uint32_t aoff = (uint32_t)((wm * (MT * 16) + (lane & 15)) * RS + ((lane >> 4) << 4));
    const uint32_t bi = lane >> 3;
    const uint32_t boff = (uint32_t)((wn * (NT * 8) + ((bi >> 1) << 3) + (lane & 7)) * RS +
                                     ((bi & 1) << 4));

    issue_chunk<BROWS>(smb, PA, PB, Ah, Al, lda, Bh, Bl, ldb, 0, tid);
    for (int c = 0; c < nchunks; ++c) {
        CPA_WAIT(0);
        __syncthreads();
        if (c + 1 < nchunks)
            issue_chunk<BROWS>(smb + ((c + 1) & 1) * BUF, PA, PB, Ah, Al, lda, Bh, Bl, ldb,
                               c + 1, tid);
        const uint32_t AHb = smb + (c & 1) * BUF, ALb = AHb + PA;
        const uint32_t BHb = AHb + 2 * PA, BLb = BHb + PB;
#pragma unroll
        for (int s = 0; s < 2; ++s) {
            uint32_t ah[MT][4], al[MT][4];
            uint32_t bh[(NT + 1) / 2][4], bl[(NT + 1) / 2][4];
            const uint32_t so = s * 32;
#pragma unroll
            for (int mt = 0; mt < MT; ++mt) {
                LDSM4(ah[mt], AHb + aoff + mt * 16 * RS + so);
                LDSM4(al[mt], ALb + aoff + mt * 16 * RS + so);
            }
#pragma unroll
            for (int p = 0; p < (NT + 1) / 2; ++p) {
                LDSM4(bh[p], BHb + boff + p * 16 * RS + so);
                LDSM4(bl[p], BLb + boff + p * 16 * RS + so);
            }
#pragma unroll
            for (int mt = 0; mt < MT; ++mt)
#pragma unroll
                for (int nt = 0; nt < NT; ++nt) {
                    const uint32_t b0h = bh[nt >> 1][(nt & 1) * 2];
                    const uint32_t b1h = bh[nt >> 1][(nt & 1) * 2 + 1];
                    const uint32_t b0l = bl[nt >> 1][(nt & 1) * 2];
                    const uint32_t b1l = bl[nt >> 1][(nt & 1) * 2 + 1];
                    MMA(acc[mt][nt], ah[mt], b0h, b1h);   // hi*hi
                    MMA(acc[mt][nt], al[mt], b0h, b1h);   // lo*hi
                    MMA(acc[mt][nt], ah[mt], b0l, b1l);   // hi*lo
                }
        }
    }
    __syncthreads();   // protect smem reuse by epilogues
}

// ---------------------------------------------------------------------------
// Input projections, merged: blockIdx.z = 0 (q->Wk->g_q), 1 (k->Wk->g_k),
// 2 (v->Wv->g_vT transposed).
// ---------------------------------------------------------------------------
__global__ __launch_bounds__(256, 2) void proj_in(const float* __restrict__ bk,
                                                  const float* __restrict__ bv) {
    extern __shared__ __align__(16) char sm[];
    const uint32_t smb = smem_u32(sm);
    const int tid = threadIdx.x, wid = tid >> 5, lane = tid & 31;
    const int wm = wid & 1, wn = wid >> 1;
    const int bm = blockIdx.y * 128, bn = blockIdx.x * 128;
    const int z = blockIdx.z;

    const float* bias = (z == 2) ? bv : bk;
    const int bsel = (z == 2) ? 1 : 0;
    const __nv_bfloat16* Ah = g_inh + (size_t)z * BSq * Eq + (size_t)bm * Eq;
    const __nv_bfloat16* Al = g_inl + (size_t)z * BSq * Eq + (size_t)bm * Eq;
    const __nv_bfloat16* Bh = g_wh + (size_t)bsel * Eq * Eq + (size_t)bn * Eq;
    const __nv_bfloat16* Bl = g_wl + (size_t)bsel * Eq * Eq + (size_t)bn * Eq;

    float acc[4][4][4];
#pragma unroll
    for (int a = 0; a < 4; ++a)
#pragma unroll
        for (int b = 0; b < 4; ++b)
#pragma unroll
            for (int c = 0; c < 4; ++c) acc[a][b][c] = 0.f;

    mma_core<128, 4, 4, 2>(smb, Ah, Al, Eq, Bh, Bl, Eq, Eq / 32, tid, acc);

    if (z != 2) {
        __nv_bfloat16* Ch = (z == 0) ? g_qh : g_kh;
        __nv_bfloat16* Cl = (z == 0) ? g_ql : g_kl;
#pragma unroll
        for (int mt = 0; mt < 4; ++mt)
#pragma unroll
            for (int nt = 0; nt < 4; ++nt) {
                const int row = bm + wm * 64 + mt * 16 + (lane >> 2);
                const int col = bn + wn * 32 + nt * 8 + ((lane & 3) << 1);
                const float2 bb = *(const float2*)(bias + col);
                st_split2(Ch, Cl, (size_t)row * Eq + col,
                          acc[mt][nt][0] + bb.x, acc[mt][nt][1] + bb.y);
                st_split2(Ch, Cl, (size_t)(row + 8) * Eq + col,
                          acc[mt][nt][2] + bb.x, acc[mt][nt][3] + bb.y);
            }
    } else {
        // transpose through smem into g_vT planes [bh][d][s]
        float (*smt)[65] = (float(*)[65])sm;
#pragma unroll
        for (int hf = 0; hf < 2; ++hf) {
            if ((wn >> 1) == hf) {
#pragma unroll
                for (int mt = 0; mt < 4; ++mt)
#pragma unroll
                    for (int nt = 0; nt < 4; ++nt) {
                        const int row = wm * 64 + mt * 16 + (lane >> 2);
                        const int colL = (wn & 1) * 32 + nt * 8 + ((lane & 3) << 1);
                        const int colG = bn + hf * 64 + colL;
                        const float2 bb = *(const float2*)(bias + colG);
                        smt[row][colL] = acc[mt][nt][0] + bb.x;
                        smt[row][colL + 1] = acc[mt][nt][1] + bb.y;
                        smt[row + 8][colL] = acc[mt][nt][2] + bb.x;
                        smt[row + 8][colL + 1] = acc[mt][nt][3] + bb.y;
                    }
            }
            __syncthreads();
            {
                const int colL = tid & 63, seg = (tid >> 6) << 5;
                const int n2 = bn + hf * 64 + colL;
                const size_t dbase = ((size_t)((bm >> 10) * 8 + (n2 >> 6)) << 16) +
                                     ((size_t)(n2 & 63) << 10) + (bm & 1023) + seg;
#pragma unroll
                for (int i = 0; i < 8; ++i) {
                    const float a0 = smt[seg + 4 * i][colL], a1 = smt[seg + 4 * i + 1][colL];
                    const float a2 = smt[seg + 4 * i + 2][colL], a3 = smt[seg + 4 * i + 3][colL];
                    st_split2(g_vth, g_vtl, dbase + 4 * i, a0, a1);
                    st_split2(g_vth, g_vtl, dbase + 4 * i + 2, a2, a3);
                }
            }
            __syncthreads();
        }
    }
}

// ---------------------------------------------------------------------------
// Output projection: d_out = attn_out @ Wo^T + bo  (fp32 result)
// ---------------------------------------------------------------------------
__global__ __launch_bounds__(256, 2) void proj_out(const float* __restrict__ bias,
                                                   float* __restrict__ Cp) {
    extern __shared__ __align__(16) char sm[];
    const uint32_t smb = smem_u32(sm);
    const int tid = threadIdx.x, wid = tid >> 5, lane = tid & 31;
    const int wm = wid & 1, wn = wid >> 1;
    const int bm = blockIdx.y * 128, bn = blockIdx.x * 128;

    const __nv_bfloat16* Ah = g_ah + (size_t)bm * Eq;
    const __nv_bfloat16* Al = g_al + (size_t)bm * Eq;
    const __nv_bfloat16* Bh = g_wh + (size_t)2 * Eq * Eq + (size_t)bn * Eq;
    const __nv_bfloat16* Bl = g_wl + (size_t)2 * Eq * Eq + (size_t)bn * Eq;

    float acc[4][4][4];
#pragma unroll
    for (int a = 0; a < 4; ++a)
#pragma unroll
        for (int b = 0; b < 4; ++b)
#pragma unroll
            for (int c = 0; c < 4; ++c) acc[a][b][c] = 0.f;

    mma_core<128, 4, 4, 2>(smb, Ah, Al, Eq, Bh, Bl, Eq, Eq / 32, tid, acc);

#pragma unroll
    for (int mt = 0; mt < 4; ++mt)
#pragma unroll
        for (int nt = 0; nt < 4; ++nt) {
            const int row = bm + wm * 64 + mt * 16 + (lane >> 2);
            const int col = bn + wn * 32 + nt * 8 + ((lane & 3) << 1);
            const float2 bb = *(const float2*)(bias + col);
            float2 o0, o1;
            o0.x = acc[mt][nt][0] + bb.x; o0.y = acc[mt][nt][1] + bb.y;
            o1.x = acc[mt][nt][2] + bb.x; o1.y = acc[mt][nt][3] + bb.y;
            *(float2*)(Cp + (size_t)row * Eq + col) = o0;
            *(float2*)(Cp + (size_t)(row + 8) * Eq + col) = o1;
        }
}

// ---------------------------------------------------------------------------
// QK^T: S = (1/8) q . k^T per (b,h); triangular grid (36 live tiles per bh).
// ---------------------------------------------------------------------------
__global__ __launch_bounds__(256, 2) void qk_mma() {
    // map t in [0,36) -> (by, bx) with bx <= by, t = by*(by+1)/2 + bx
    const int t = blockIdx.x;
    int by = (int)((sqrtf(8.f * t + 1.f) - 1.f) * 0.5f);
    while ((by + 1) * (by + 2) / 2 <= t) ++by;
    while (by * (by + 1) / 2 > t) --by;
    const int bx = t - by * (by + 1) / 2;

    extern __shared__ __align__(16) char sm[];
    const uint32_t smb = smem_u32(sm);
    const int tid = threadIdx.x, wid = tid >> 5, lane = tid & 31;
    const int wm = wid & 1, wn = wid >> 1;
    const int bh = blockIdx.z, b = bh >> 3, h = bh & 7;
    const int bm = by * 128, bn = bx * 128;

    const size_t abase = (size_t)(b * Sq + bm) * Eq + h * Dq;
    const size_t bbase = (size_t)(b * Sq + bn) * Eq + h * Dq;

    float acc[4][4][4];
#pragma unroll
    for (int a = 0; a < 4; ++a)
#pragma unroll
        for (int c = 0; c < 4; ++c)
#pragma unroll
            for (int d = 0; d < 4; ++d) acc[a][c][d] = 0.f;

    mma_core<128, 4, 4, 2>(smb, g_qh + abase, g_ql + abase, Eq,
                           g_kh + bbase, g_kl + bbase, Eq, Dq / 32, tid, acc);

    float* S = g_s + ((size_t)bh << 20);
#pragma unroll
    for (int mt = 0; mt < 4; ++mt)
#pragma unroll
        for (int nt = 0; nt < 4; ++nt) {
            const int row = bm + wm * 64 + mt * 16 + (lane >> 2);
            const int col = bn + wn * 32 + nt * 8 + ((lane & 3) << 1);
            float2 o0, o1;
            o0.x = acc[mt][nt][0] * 0.125f; o0.y = acc[mt][nt][1] * 0.125f;
            o1.x = acc[mt][nt][2] * 0.125f; o1.y = acc[mt][nt][3] * 0.125f;
            *(float2*)(S + (size_t)row * Sq + col) = o0;
            *(float2*)(S + (size_t)(row + 8) * Sq + col) = o1;
        }
}

// ---------------------------------------------------------------------------
// PV: out[i,d] = sum_j P[i,j] * VT[d,j].  BN=64, K extent = bm+128 (causal).
// Warp grid 4m x 2n (MT=2, NT=4).
// ---------------------------------------------------------------------------
__global__ __launch_bounds__(256, 2) void pv_mma() {
    extern __shared__ __align__(16) char sm[];
    const uint32_t smb = smem_u32(sm);
    const int tid = threadIdx.x, wid = tid >> 5, lane = tid & 31;
    const int wm = wid & 3, wn = wid >> 2;
    const int bh = blockIdx.y, b = bh >> 3, h = bh & 7;
    const int bm = (7 - (int)blockIdx.x) * 128;   // heavy tiles first

    const size_t pbase = ((size_t)bh << 20) + (size_t)bm * Sq;
    const size_t vbase = (size_t)bh * (Dq * Sq);

    float acc[2][4][4];
#pragma unroll
    for (int a = 0; a < 2; ++a)
#pragma unroll
        for (int c = 0; c < 4; ++c)
#pragma unroll
            for (int d = 0; d < 4; ++d) acc[a][c][d] = 0.f;

    mma_core<64, 2, 4, 4>(smb, g_ph + pbase, g_pl + pbase, Sq,
                          g_vth + vbase, g_vtl + vbase, Sq, bm / 32 + 4, tid, acc);

#pragma unroll
    for (int mt = 0; mt < 2; ++mt)
#pragma unroll
        for (int nt = 0; nt < 4; ++nt) {
            const int row = b * Sq + bm + wm * 32 + mt * 16 + (lane >> 2);
            const int col = h * Dq + wn * 32 + nt * 8 + ((lane & 3) << 1);
            st_split2(g_ah, g_al, (size_t)row * Eq + col, acc[mt][nt][0], acc[mt][nt][1]);
            st_split2(g_ah, g_al, (size_t)(row + 8) * Eq + col, acc[mt][nt][2], acc[mt][nt][3]);
        }
}

// ---------------------------------------------------------------------------
// Softmax + decay, bucketed by row length (no max-subtraction; scores O(1)).
// FUSED: one launch, heavy buckets first, short-row blocks backfill the tail.
// ---------------------------------------------------------------------------
__device__ __forceinline__ float wsum(float v) {
#pragma unroll
    for (int o = 16; o > 0; o >>= 1) v += __shfl_xor_sync(0xffffffffu, v, o);
    return v;
}

template<int NS>
__device__ __forceinline__ void softmax_body(const float* __restrict__ gammas,
                                             int local_blk) {
    const int warp = threadIdx.x >> 5;
    const int lane = threadIdx.x & 31;
    const int glob = local_blk * 8 + warp;
    const int bh = glob >> 8;
    const int ibase = (NS - 8) * 32;          // NS=8->0, 16->256, 24->512, 32->768
    const int i = ibase + (glob & 255);
    const int r = bh * Sq + i;
    const int h = bh & (Hq - 1);
    const float* Srow = g_s + (size_t)r * Sq;

    const float gv = gammas[h];
    const float gamma = -(fmaxf(gv, 0.f) + log1pf(__expf(-fabsf(gv))));
    const float NEGINF = -INFINITY;

    const int j0 = lane * NS;
    float s[NS];
    if (j0 <= i) {
#pragma unroll
        for (int t = 0; t < NS / 4; t++) ((float4*)s)[t] = ((const float4*)(Srow + j0))[t];
#pragma unroll
        for (int t = 0; t < NS; t++) if (j0 + t > i) s[t] = NEGINF;
    } else {
#pragma unroll
        for (int t = 0; t < NS; t++) s[t] = NEGINF;
    }

    float p[NS];
    float ls = 0.f;
#pragma unroll
    for (int t = 0; t < NS; t++) { p[t] = __expf(s[t]); ls += p[t]; }
    const float inv1 = 1.f / wsum(ls);

#pragma unroll
    for (int t = 1; t < NS; t++) p[t] += p[t - 1];
    float tot = p[NS - 1];
    float x = tot;
#pragma unroll
    for (int off = 1; off < 32; off <<= 1) {
        const float tv = __shfl_up_sync(0xffffffffu, x, off);
        if (lane >= off) x += tv;
    }
    const float excl = x - tot;

#pragma unroll
    for (int t = 0; t < NS; t++) {
        const int j = j0 + t;
        const float Cj = (excl + p[t]) * inv1;
        const float pd = fmaxf((1.f - Cj) * (float)(i - j), 0.f);
        float eff = __expf(gamma * sqrtf(pd));
        eff = fminf(fmaxf(eff, 1e-5f), 1e5f);
        s[t] *= eff;
    }

    float l2 = 0.f;
#pragma unroll
    for (int t = 0; t < NS; t++) { p[t] = __expf(s[t]); l2 += p[t]; }
    const float scale = ((i == 0) ? 0.f : 1.f) / wsum(l2);
#pragma unroll
    for (int t = 0; t < NS; t++) p[t] *= scale;

    if (j0 < (((i >> 7) + 1) << 7)) {   // pv reads only up to the row's diagonal tile
        uint32_t hw[NS / 2], lw[NS / 2];
#pragma unroll
        for (int t = 0; t < NS; t += 2) {
            __nv_bfloat162 h2 = __floats2bfloat162_rn(p[t], p[t + 1]);
            float2 f = __bfloat1622float2(h2);
            __nv_bfloat162 l2v = __floats2bfloat162_rn(p[t] - f.x, p[t + 1] - f.y);
            hw[t >> 1] = *(uint32_t*)&h2;
            lw[t >> 1] = *(uint32_t*)&l2v;
        }
        uint4* dh = (uint4*)(g_ph + (size_t)r * Sq + j0);
        uint4* dl = (uint4*)(g_pl + (size_t)r * Sq + j0);
#pragma unroll
        for (int w = 0; w < NS / 8; ++w) { dh[w] = ((uint4*)hw)[w]; dl[w] = ((uint4*)lw)[w]; }
    }
}

__global__ __launch_bounds__(256) void softmax_decay_fused(const float* __restrict__ gammas) {
    const int blk = blockIdx.x;
    if (blk < 2048)       softmax_body<32>(gammas, blk);            // rows [768,1024), heaviest
    else if (blk < 4096)  softmax_body<24>(gammas, blk - 2048);     // rows [512, 768)
    else if (blk < 6144)  softmax_body<16>(gammas, blk - 4096);     // rows [256, 512)
    else                  softmax_body< 8>(gammas, blk - 6144);     // rows [  0, 256)
}

// ---------------------------------------------------------------------------
extern "C" void kernel_launch(void* const* d_in, const int* in_sizes, int n_in,
                              void* d_out, int out_size) {
    const float* q      = (const float*)d_in[0];
    const float* k      = (const float*)d_in[1];
    const float* v      = (const float*)d_in[2];
    const float* Wk     = (const float*)d_in[3];
    const float* bk     = (const float*)d_in[4];
    const float* Wv     = (const float*)d_in[5];
    const float* bv     = (const float*)d_in[6];
    const float* Wo     = (const float*)d_in[7];
    const float* bo     = (const float*)d_in[8];
    const float* gammas = (const float*)d_in[9];

    const int SM_128 = 2 * (2 * 128 * RS + 2 * 128 * RS);  // 81920
    const int SM_64  = 2 * (2 * 128 * RS + 2 * 64 * RS);   // 61440
    cudaFuncSetAttribute(proj_in,  cudaFuncAttributeMaxDynamicSharedMemorySize, SM_128);
    cudaFuncSetAttribute(proj_out, cudaFuncAttributeMaxDynamicSharedMemorySize, SM_128);
    cudaFuncSetAttribute(qk_mma,   cudaFuncAttributeMaxDynamicSharedMemorySize, SM_128);
    cudaFuncSetAttribute(pv_mma,   cudaFuncAttributeMaxDynamicSharedMemorySize, SM_64);

    cvt_all<<<1024, 256>>>(q, k, v, Wk, Wv, Wo);
    proj_in<<<dim3(4, 64, 3), 256, SM_128>>>(bk, bv);                // g_q, g_k, g_vT planes
    qk_mma<<<dim3(36, 1, 64), 256, SM_128>>>();                      // g_s = scores (triangular)
    softmax_decay_fused<<<8192, 256>>>(gammas);                      // P planes (one launch)
    pv_mma<<<dim3(8, 64), 256, SM_64>>>();                           // g_a planes
    proj_out<<<dim3(4, 64), 256, SM_128>>>(bo, (float*)d_out);       // final fp32
}